// round 1
// baseline (speedup 1.0000x reference)
#include <cuda_runtime.h>

#define NE 32
#define NA 8
#define KD 8
#define ED 16
#define LN2 0.69314718055994531f

__global__ __launch_bounds__(1024, 1)
void omni_kernel(const float* __restrict__ dn, const float* __restrict__ de,
                 const float* __restrict__ Xe, const float* __restrict__ Yn,
                 const float* __restrict__ w1, const float* __restrict__ wb1,
                 const float* __restrict__ w2, const float* __restrict__ wb2,
                 const float* __restrict__ hsw, const float* __restrict__ hsb,
                 const float* __restrict__ haw, const float* __restrict__ hab,
                 const float* __restrict__ gw, const float* __restrict__ gb,
                 const float* __restrict__ orb, float* __restrict__ out)
{
    const int b    = blockIdx.x;
    const int lane = threadIdx.x;   // partner electron j (0..31)
    const int i    = threadIdx.y;   // electron i (0..31), one warp per i
    const int tid  = (i << 5) | lane;

    __shared__ float sw1[2][24];            // [n][d*6+u]
    __shared__ float swb1[2][6];
    __shared__ float sw2[2][48];            // [n][u*8+k]
    __shared__ float swb2[2][8];            // bias with -ln2*sum(w2) folded in
    __shared__ float shw[2][2][128];        // [n][same/anti][d*8+k]
    __shared__ float shb[2][2][8];
    __shared__ float sgw[2][128];           // [n][k*16+t]
    __shared__ float sgb[2][16];
    __shared__ float sY[64];                // [m*8+k]
    __shared__ float sorb[16];
    __shared__ float sx[NE][ED];            // electron embeddings
    __shared__ float sc[2][KD][NE + 1];     // coefficient mats: [U/D][k][j], padded
    __shared__ float sznuc[2][NE][KD];      // nuclear message per interaction
    __shared__ float spart[16];

    // ---- stage weights into smem (broadcast-read later) ----
    if (tid < 48)  ((float*)sw1)[tid]  = w1[tid];
    if (tid < 12)  ((float*)swb1)[tid] = wb1[tid];
    if (tid < 96)  ((float*)sw2)[tid]  = w2[tid];
    if (tid < 16)  ((float*)swb2)[tid] = wb2[tid];
    if (tid < 256) { int n = tid >> 7, r = tid & 127; shw[n][0][r] = hsw[tid]; shw[n][1][r] = haw[tid]; }
    if (tid < 16)  { int n = tid >> 3, k = tid & 7;   shb[n][0][k] = hsb[tid]; shb[n][1][k] = hab[tid]; }
    if (tid < 256) ((float*)sgw)[tid]  = gw[tid];
    if (tid < 32)  ((float*)sgb)[tid]  = gb[tid];
    if (tid < 64)  sY[tid]   = Yn[tid];
    if (tid < 16)  sorb[tid] = orb[tid];
    if (tid < NE * ED) sx[tid >> 4][tid & 15] = Xe[tid & 15];   // all electrons share X[0]
    __syncthreads();

    // fold SSP's -ln2 into layer-2 bias:  (a-ln2)@w2 + b2 = a@w2 + (b2 - ln2*sum_u w2)
    if (tid < 16) {
        int n = tid >> 3, k = tid & 7;
        float s = 0.f;
        #pragma unroll
        for (int u = 0; u < 6; u++) s += sw2[n][u * 8 + k];
        swb2[n][k] -= LN2 * s;
    }

    // electron-pair distance features: held in registers for both interactions
    const float4 ee = *reinterpret_cast<const float4*>(
        &de[(((size_t)b * NE + i) * NE + lane) << 2]);
    __syncthreads();

    // ---- nuclear messages (independent of x): precompute for both interactions ----
    if (tid < 512) {
        const int n  = tid >> 8;          // interaction
        const int ii = (tid >> 3) & 31;   // electron
        const int m  = tid & 7;           // atom
        const float4 en = *reinterpret_cast<const float4*>(
            &dn[(((size_t)b * NE + ii) * NA + m) << 2]);
        float a[6];
        #pragma unroll
        for (int u = 0; u < 6; u++) {
            float v = swb1[n][u];
            v = fmaf(en.x, sw1[n][u],      v);
            v = fmaf(en.y, sw1[n][6 + u],  v);
            v = fmaf(en.z, sw1[n][12 + u], v);
            v = fmaf(en.w, sw1[n][18 + u], v);
            a[u] = __logf(1.0f + __expf(v));   // softplus; -ln2 folded into bias
        }
        #pragma unroll
        for (int k = 0; k < 8; k++) {
            float v = swb2[n][k];
            #pragma unroll
            for (int u = 0; u < 6; u++) v = fmaf(a[u], sw2[n][u * 8 + k], v);
            v *= sY[m * 8 + k];
            v += __shfl_xor_sync(0xffffffffu, v, 4);
            v += __shfl_xor_sync(0xffffffffu, v, 2);
            v += __shfl_xor_sync(0xffffffffu, v, 1);
            if (m == 0) sznuc[n][ii][k] = v;
        }
    }
    __syncthreads();

    const int   g        = (i >= 16) ? 1 : 0;
    const float selfmask = (lane == i) ? 0.0f : 1.0f;

    #pragma unroll
    for (int n = 0; n < 2; n++) {
        // message features hs/ha from current x; scatter into cU/cD so that the
        // consumer warp reads a single spin-correct coefficient row (no per-lane select).
        if (lane < 16) {
            const int s = lane >> 3;   // 0 = hs (same), 1 = ha (anti)
            const int k = lane & 7;
            float v = shb[n][s][k];
            #pragma unroll
            for (int d = 0; d < 16; d++)
                v = fmaf(sx[i][d], shw[n][s][(d << 3) + k], v);
            sc[s ^ g][k][i] = v;   // cU[k][j]: hs for j<16, ha for j>=16 ; cD flipped
        }
        __syncthreads();

        // pair MLP: 4 -> 6 (SSP) -> 8
        float a[6];
        #pragma unroll
        for (int u = 0; u < 6; u++) {
            float v = swb1[n][u];
            v = fmaf(ee.x, sw1[n][u],      v);
            v = fmaf(ee.y, sw1[n][6 + u],  v);
            v = fmaf(ee.z, sw1[n][12 + u], v);
            v = fmaf(ee.w, sw1[n][18 + u], v);
            a[u] = __logf(1.0f + __expf(v));
        }
        float z[8];
        #pragma unroll
        for (int k = 0; k < 8; k++) {
            float v = swb2[n][k];
            #pragma unroll
            for (int u = 0; u < 6; u++) v = fmaf(a[u], sw2[n][u * 8 + k], v);
            float ctr = v * (sc[g][k][lane] * selfmask);
            // butterfly reduce over j: result broadcast to all lanes
            ctr += __shfl_xor_sync(0xffffffffu, ctr, 16);
            ctr += __shfl_xor_sync(0xffffffffu, ctr, 8);
            ctr += __shfl_xor_sync(0xffffffffu, ctr, 4);
            ctr += __shfl_xor_sync(0xffffffffu, ctr, 2);
            ctr += __shfl_xor_sync(0xffffffffu, ctr, 1);
            z[k] = ctr + sznuc[n][i][k];
        }

        // residual update: x += z @ g_w + g_b   (lanes 0..15 each produce one dim)
        if (lane < 16) {
            float dlt = sgb[n][lane];
            #pragma unroll
            for (int k = 0; k < 8; k++)
                dlt = fmaf(z[k], sgw[n][(k << 4) + lane], dlt);
            sx[i][lane] += dlt;
        }
        __syncthreads();
    }

    // ---- orbital projection + sum over electrons ----
    if (i < 16) {   // tid < 512 covers all 32x16 embedding entries
        float v = sx[tid >> 4][tid & 15] * sorb[tid & 15];
        v += __shfl_xor_sync(0xffffffffu, v, 16);
        v += __shfl_xor_sync(0xffffffffu, v, 8);
        v += __shfl_xor_sync(0xffffffffu, v, 4);
        v += __shfl_xor_sync(0xffffffffu, v, 2);
        v += __shfl_xor_sync(0xffffffffu, v, 1);
        if (lane == 0) spart[i] = v;
    }
    __syncthreads();
    if (tid == 0) {
        float s = 0.f;
        #pragma unroll
        for (int w = 0; w < 16; w++) s += spart[w];
        out[b] = s;
    }
}

extern "C" void kernel_launch(void* const* d_in, const int* in_sizes, int n_in,
                              void* d_out, int out_size)
{
    const float* dn   = (const float*)d_in[0];
    const float* de   = (const float*)d_in[1];
    const float* Xe   = (const float*)d_in[2];
    const float* Yn   = (const float*)d_in[3];
    const float* w1   = (const float*)d_in[4];
    const float* wb1  = (const float*)d_in[5];
    const float* w2   = (const float*)d_in[6];
    const float* wb2  = (const float*)d_in[7];
    const float* hsw  = (const float*)d_in[8];
    const float* hsb  = (const float*)d_in[9];
    const float* haw  = (const float*)d_in[10];
    const float* hab  = (const float*)d_in[11];
    const float* gw   = (const float*)d_in[12];
    const float* gb   = (const float*)d_in[13];
    const float* orb  = (const float*)d_in[14];
    float* out = (float*)d_out;

    const int B = in_sizes[0] / (NE * NA * 4);   // dists_nuc: (B,32,8,4)

    dim3 blk(32, 32);
    omni_kernel<<<B, blk>>>(dn, de, Xe, Yn, w1, wb1, w2, wb2,
                            hsw, hsb, haw, hab, gw, gb, orb, out);
}

// round 2
// speedup vs baseline: 2.1206x; 2.1206x over previous
#include <cuda_runtime.h>

#define NE 32
#define NA 8
#define KD 8
#define ED 16
#define LN2 0.69314718055994531f

// Warp-uniform weights: constant bank -> LDCU (UR regs, floor=1, off the LSU path)
__constant__ float cW1[2][24];   // [n][d*6+u]
__constant__ float cB1[2][6];
__constant__ float cW2[2][48];   // [n][u*8+k]
__constant__ float cB2[2][8];

__device__ __forceinline__ float ssp_f(float v) {
    // softplus(v) - ln2 = ln2 * (log2(1 + e^v) - 1)
    return fmaf(__log2f(1.0f + __expf(v)), LN2, -LN2);
}

__global__ __launch_bounds__(1024, 1)
void omni_kernel(const float* __restrict__ dn, const float* __restrict__ de,
                 const float* __restrict__ Xe, const float* __restrict__ Yn,
                 const float* __restrict__ hsw, const float* __restrict__ hsb,
                 const float* __restrict__ haw, const float* __restrict__ hab,
                 const float* __restrict__ gw, const float* __restrict__ gb,
                 const float* __restrict__ orb, float* __restrict__ out)
{
    const int b    = blockIdx.x;
    const int lane = threadIdx.x;   // partner electron j
    const int i    = threadIdx.y;   // electron i, one warp per i
    const int tid  = (i << 5) | lane;
    const unsigned M = 0xffffffffu;

    __shared__ float shw[2][2][128];        // [n][same/anti][d*8+k]  (lane-indexed)
    __shared__ float shb[2][2][8];
    __shared__ float sgw[2][128];           // [n][k*16+t]
    __shared__ float sgb[2][16];
    __shared__ float sY[64];                // [m*8+k]
    __shared__ float sorb[16];
    __shared__ float sx[NE][ED];            // electron embeddings
    __shared__ float sc[2][KD][NE + 1];     // coefficient mats: [U/D][k][j]
    __shared__ float sznuc[2][NE][KD];      // nuclear messages
    __shared__ float spart[16];

    // ---- stage lane-indexed weights into smem ----
    if (tid < 256) { int n = tid >> 7, r = tid & 127; shw[n][0][r] = hsw[tid]; shw[n][1][r] = haw[tid]; }
    if (tid < 16)  { int n = tid >> 3, k = tid & 7;   shb[n][0][k] = hsb[tid]; shb[n][1][k] = hab[tid]; }
    if (tid < 256) ((float*)sgw)[tid]  = gw[tid];
    if (tid < 32)  ((float*)sgb)[tid]  = gb[tid];
    if (tid < 64)  sY[tid]   = Yn[tid];
    if (tid < 16)  sorb[tid] = orb[tid];
    if (tid < NE * ED) sx[tid >> 4][tid & 15] = Xe[tid & 15];   // all share X[0]

    // electron-pair distance features: registers for both interactions
    const float4 ee = *reinterpret_cast<const float4*>(
        &de[(((size_t)b * NE + i) * NE + lane) << 2]);
    __syncthreads();

    // ---- nuclear messages (x-independent): both interactions up front ----
    if (tid < 512) {
        const int n  = tid >> 8;
        const int ii = (tid >> 3) & 31;
        const int m  = tid & 7;
        const float4 en = *reinterpret_cast<const float4*>(
            &dn[(((size_t)b * NE + ii) * NA + m) << 2]);
        float a[6];
        #pragma unroll
        for (int u = 0; u < 6; u++) {
            float v = cB1[n][u];
            v = fmaf(en.x, cW1[n][u],      v);
            v = fmaf(en.y, cW1[n][6 + u],  v);
            v = fmaf(en.z, cW1[n][12 + u], v);
            v = fmaf(en.w, cW1[n][18 + u], v);
            a[u] = ssp_f(v);
        }
        float c[8];
        #pragma unroll
        for (int k = 0; k < 8; k++) {
            float v = cB2[n][k];
            #pragma unroll
            for (int u = 0; u < 6; u++) v = fmaf(a[u], cW2[n][u * 8 + k], v);
            c[k] = v * sY[m * 8 + k];
        }
        // fold 8 values over the 8-lane atom group: k(m) ends equal to m
        const bool h4 = (m & 4), h2 = (m & 2), h1 = (m & 1);
        float s;
        #pragma unroll
        for (int q = 0; q < 4; q++) {
            s = __shfl_xor_sync(M, h4 ? c[q] : c[q + 4], 4);
            c[q] = (h4 ? c[q + 4] : c[q]) + s;
        }
        #pragma unroll
        for (int q = 0; q < 2; q++) {
            s = __shfl_xor_sync(M, h2 ? c[q] : c[q + 2], 2);
            c[q] = (h2 ? c[q + 2] : c[q]) + s;
        }
        s = __shfl_xor_sync(M, h1 ? c[0] : c[1], 1);
        c[0] = (h1 ? c[1] : c[0]) + s;
        sznuc[n][ii][m] = c[0];
    }
    __syncthreads();

    const int   g        = (i >= 16) ? 1 : 0;
    const float selfmask = (lane == i) ? 0.0f : 1.0f;
    const int   klane    = (lane >> 2) & 7;     // k owned by this lane after folding

    #pragma unroll
    for (int n = 0; n < 2; n++) {
        // h features: scatter into cU/cD so consumer reads one spin-correct row
        if (lane < 16) {
            const int s = lane >> 3;   // 0 = same, 1 = anti
            const int k = lane & 7;
            float v = shb[n][s][k];
            #pragma unroll
            for (int d = 0; d < 16; d++)
                v = fmaf(sx[i][d], shw[n][s][(d << 3) + k], v);
            sc[s ^ g][k][i] = v;
        }
        __syncthreads();

        // pair MLP 4 -> 6 (SSP) -> 8, weights from constant bank (LDCU/UR)
        float a[6];
        #pragma unroll
        for (int u = 0; u < 6; u++) {
            float v = cB1[n][u];
            v = fmaf(ee.x, cW1[n][u],      v);
            v = fmaf(ee.y, cW1[n][6 + u],  v);
            v = fmaf(ee.z, cW1[n][12 + u], v);
            v = fmaf(ee.w, cW1[n][18 + u], v);
            a[u] = ssp_f(v);
        }
        float c[8];
        #pragma unroll
        for (int k = 0; k < 8; k++) {
            float v = cB2[n][k];
            #pragma unroll
            for (int u = 0; u < 6; u++) v = fmaf(a[u], cW2[n][u * 8 + k], v);
            c[k] = v * (sc[g][k][lane] * selfmask);
        }

        // fold-reduce over j: 4+2+1 value-folding + 2 finishing rounds (9 shuffles)
        {
            const bool h16 = (lane & 16), h8 = (lane & 8), h4 = (lane & 4);
            float s;
            #pragma unroll
            for (int q = 0; q < 4; q++) {
                s = __shfl_xor_sync(M, h16 ? c[q] : c[q + 4], 16);
                c[q] = (h16 ? c[q + 4] : c[q]) + s;
            }
            #pragma unroll
            for (int q = 0; q < 2; q++) {
                s = __shfl_xor_sync(M, h8 ? c[q] : c[q + 2], 8);
                c[q] = (h8 ? c[q + 2] : c[q]) + s;
            }
            s = __shfl_xor_sync(M, h4 ? c[0] : c[1], 4);
            c[0] = (h4 ? c[1] : c[0]) + s;
            c[0] += __shfl_xor_sync(M, c[0], 2);
            c[0] += __shfl_xor_sync(M, c[0], 1);
        }
        // lane 4k holds z[k]; add nuclear message, then gather full z to all lanes
        c[0] += sznuc[n][i][klane];
        float z[8];
        #pragma unroll
        for (int k = 0; k < 8; k++)
            z[k] = __shfl_sync(M, c[0], k << 2);

        // residual update: x += z @ g_w + g_b  (lanes 0..15, one dim each)
        if (lane < 16) {
            float dlt = sgb[n][lane];
            #pragma unroll
            for (int k = 0; k < 8; k++)
                dlt = fmaf(z[k], sgw[n][(k << 4) + lane], dlt);
            sx[i][lane] += dlt;
        }
        __syncthreads();
    }

    // ---- orbital projection + sum over electrons ----
    if (i < 16) {
        float v = sx[tid >> 4][tid & 15] * sorb[tid & 15];
        v += __shfl_xor_sync(M, v, 16);
        v += __shfl_xor_sync(M, v, 8);
        v += __shfl_xor_sync(M, v, 4);
        v += __shfl_xor_sync(M, v, 2);
        v += __shfl_xor_sync(M, v, 1);
        if (lane == 0) spart[i] = v;
    }
    __syncthreads();
    if (tid == 0) {
        float s = 0.f;
        #pragma unroll
        for (int w = 0; w < 16; w++) s += spart[w];
        out[b] = s;
    }
}

extern "C" void kernel_launch(void* const* d_in, const int* in_sizes, int n_in,
                              void* d_out, int out_size)
{
    const float* dn   = (const float*)d_in[0];
    const float* de   = (const float*)d_in[1];
    const float* Xe   = (const float*)d_in[2];
    const float* Yn   = (const float*)d_in[3];
    const float* hsw  = (const float*)d_in[8];
    const float* hsb  = (const float*)d_in[9];
    const float* haw  = (const float*)d_in[10];
    const float* hab  = (const float*)d_in[11];
    const float* gw   = (const float*)d_in[12];
    const float* gb   = (const float*)d_in[13];
    const float* orb  = (const float*)d_in[14];
    float* out = (float*)d_out;

    // warp-uniform weights -> constant bank (DtoD async copies; graph-capturable)
    cudaMemcpyToSymbolAsync(cW1, d_in[4], 48 * sizeof(float), 0, cudaMemcpyDeviceToDevice, 0);
    cudaMemcpyToSymbolAsync(cB1, d_in[5], 12 * sizeof(float), 0, cudaMemcpyDeviceToDevice, 0);
    cudaMemcpyToSymbolAsync(cW2, d_in[6], 96 * sizeof(float), 0, cudaMemcpyDeviceToDevice, 0);
    cudaMemcpyToSymbolAsync(cB2, d_in[7], 16 * sizeof(float), 0, cudaMemcpyDeviceToDevice, 0);

    const int B = in_sizes[0] / (NE * NA * 4);   // dists_nuc: (B,32,8,4)

    dim3 blk(32, 32);
    omni_kernel<<<B, blk>>>(dn, de, Xe, Yn,
                            hsw, hsb, haw, hab, gw, gb, orb, out);
}

// round 3
// speedup vs baseline: 2.3341x; 1.1007x over previous
#include <cuda_runtime.h>

#define NE 32
#define NA 8
#define KD 8
#define ED 16
#define LN2 0.69314718055994531f

typedef unsigned long long ull;

// Warp-uniform weights in constant bank, PRE-PAIRED layout (same bytes as inputs;
// pairs are contiguous in the original row-major tensors).
__constant__ ull cW1p[2][12];   // [n][d*3 + upair]
__constant__ ull cB1p[2][3];
__constant__ ull cW2p[2][24];   // [n][u*4 + kpair]
__constant__ ull cB2p[2][4];

__device__ __forceinline__ ull fma2(ull a, ull b, ull c) {
    ull d; asm("fma.rn.f32x2 %0,%1,%2,%3;" : "=l"(d) : "l"(a), "l"(b), "l"(c)); return d;
}
__device__ __forceinline__ ull mul2(ull a, ull b) {
    ull d; asm("mul.rn.f32x2 %0,%1,%2;" : "=l"(d) : "l"(a), "l"(b)); return d;
}
__device__ __forceinline__ ull add2(ull a, ull b) {
    ull d; asm("add.rn.f32x2 %0,%1,%2;" : "=l"(d) : "l"(a), "l"(b)); return d;
}
__device__ __forceinline__ ull pack2(float lo, float hi) {
    ull d; asm("mov.b64 %0,{%1,%2};" : "=l"(d) : "f"(lo), "f"(hi)); return d;
}
__device__ __forceinline__ void unpack2(ull v, float& lo, float& hi) {
    asm("mov.b64 {%0,%1},%2;" : "=f"(lo), "=f"(hi) : "l"(v));
}
__device__ __forceinline__ ull lds64(const float* p) {
    return *reinterpret_cast<const ull*>(p);
}
__device__ __forceinline__ float ssp_f(float v) {
    // softplus(v) - ln2 = ln2*(log2(1 + e^v) - 1)
    return fmaf(__log2f(1.0f + __expf(v)), LN2, -LN2);
}

__global__ __launch_bounds__(1024, 1)
void omni_kernel(const float* __restrict__ dn, const float* __restrict__ de,
                 const float* __restrict__ Xe, const float* __restrict__ Yn,
                 const float* __restrict__ hsw, const float* __restrict__ hsb,
                 const float* __restrict__ haw, const float* __restrict__ hab,
                 const float* __restrict__ gw, const float* __restrict__ gb,
                 const float* __restrict__ orb, float* __restrict__ out)
{
    const int b    = blockIdx.x;
    const int lane = threadIdx.x;   // partner electron j
    const int i    = threadIdx.y;   // electron i, one warp per i
    const int tid  = (i << 5) | lane;
    const unsigned M = 0xffffffffu;

    __shared__ float shwT[2][2][8][18];   // [n][s][k][d] pairs, pad->72B stride (conflict-free)
    __shared__ float shb[2][2][8];
    __shared__ float sgwT[2][16][10];     // [n][t][k] pairs, pad->40B stride
    __shared__ float sgb[2][16];
    __shared__ float sY[64];              // [m*8+k]
    __shared__ float sorb[16];
    __shared__ float sx[NE][ED];          // electron embeddings (8B-aligned rows)
    __shared__ float sc2[2][2][NE][10];   // [n][spin][j][k], pad->40B stride
    __shared__ float sznuc[2][NE][KD];    // nuclear messages (pairs 8B-aligned)
    __shared__ float spart[16];

    // ---- stage lane-indexed weights into smem (transposed for packed loads) ----
    if (tid < 512) {                       // shwT: [n][s][k][d] <- (s?haw:hsw)[n*128+d*8+k]
        const int n = tid >> 8, r = tid & 255;
        const int s = r >> 7, r2 = r & 127, k = r2 >> 4, d = r2 & 15;
        shwT[n][s][k][d] = (s ? haw : hsw)[n * 128 + d * 8 + k];
    }
    if (tid < 16)  { int n = tid >> 3, k = tid & 7; shb[n][0][k] = hsb[tid]; shb[n][1][k] = hab[tid]; }
    if (tid < 256) {                       // sgwT: [n][t][k] <- gw[n*128+k*16+t]
        const int n = tid >> 7, r = tid & 127, t = r >> 3, k = r & 7;
        sgwT[n][t][k] = gw[n * 128 + k * 16 + t];
    }
    if (tid < 32)  ((float*)sgb)[tid] = gb[tid];
    if (tid < 64)  sY[tid]   = Yn[tid];
    if (tid < 16)  sorb[tid] = orb[tid];
    if (tid < NE * ED) sx[tid >> 4][tid & 15] = Xe[tid & 15];   // all electrons share X[0]

    // pair distance features, packed as lane-dups for f32x2 math (both interactions)
    ull eed[4];
    {
        const float4 ee = *reinterpret_cast<const float4*>(
            &de[(((size_t)b * NE + i) * NE + lane) << 2]);
        eed[0] = pack2(ee.x, ee.x); eed[1] = pack2(ee.y, ee.y);
        eed[2] = pack2(ee.z, ee.z); eed[3] = pack2(ee.w, ee.w);
    }
    __syncthreads();

    // ---- nuclear messages (x-independent), both interactions ----
    if (tid < 512) {
        const int n  = tid >> 8;
        const int ii = (tid >> 3) & 31;
        const int m  = tid & 7;
        const float4 en = *reinterpret_cast<const float4*>(
            &dn[(((size_t)b * NE + ii) * NA + m) << 2]);
        ull end[4] = { pack2(en.x, en.x), pack2(en.y, en.y),
                       pack2(en.z, en.z), pack2(en.w, en.w) };
        // L1: 4 -> 6, packed over u-pairs
        float a[6];
        #pragma unroll
        for (int p = 0; p < 3; p++) {
            ull v2 = cB1p[n][p];
            #pragma unroll
            for (int d = 0; d < 4; d++) v2 = fma2(end[d], cW1p[n][d * 3 + p], v2);
            float lo, hi; unpack2(v2, lo, hi);
            a[2 * p] = ssp_f(lo); a[2 * p + 1] = ssp_f(hi);
        }
        // L2: 6 -> 8, packed over k-pairs
        ull acc[4];
        #pragma unroll
        for (int q = 0; q < 4; q++) acc[q] = cB2p[n][q];
        #pragma unroll
        for (int u = 0; u < 6; u++) {
            const ull ad = pack2(a[u], a[u]);
            #pragma unroll
            for (int q = 0; q < 4; q++) acc[q] = fma2(ad, cW2p[n][u * 4 + q], acc[q]);
        }
        #pragma unroll
        for (int q = 0; q < 4; q++) acc[q] = mul2(acc[q], lds64(&sY[m * 8 + 2 * q]));
        // fold over 8-lane atom group
        const bool h4 = (m & 4), h2 = (m & 2);
        ull s;
        #pragma unroll
        for (int q = 0; q < 2; q++) {
            s = __shfl_xor_sync(M, h4 ? acc[q] : acc[q + 2], 4);
            acc[q] = add2(h4 ? acc[q + 2] : acc[q], s);
        }
        s = __shfl_xor_sync(M, h2 ? acc[0] : acc[1], 2);
        acc[0] = add2(h2 ? acc[1] : acc[0], s);
        acc[0] = add2(acc[0], __shfl_xor_sync(M, acc[0], 1));
        const int qc = (h4 ? 2 : 0) + (h2 ? 1 : 0);
        if ((m & 1) == 0)
            *reinterpret_cast<ull*>(&sznuc[n][ii][2 * qc]) = acc[0];
    }
    __syncthreads();

    const int g     = (i >= 16) ? 1 : 0;
    const float mk  = (lane == i) ? 0.f : 1.f;
    const ull mask2 = pack2(mk, mk);
    const int qcls  = ((lane >> 3) & 2) | ((lane >> 3) & 1);   // 2*h16 + h8

    #pragma unroll
    for (int n = 0; n < 2; n++) {
        // h features -> sc2[n] (double-buffered: no end-of-loop barrier needed)
        if (lane < 16) {
            const int s = lane >> 3;
            const int k = lane & 7;
            ull acc = pack2(shb[n][s][k], 0.f);
            #pragma unroll
            for (int d2 = 0; d2 < 8; d2++)
                acc = fma2(lds64(&sx[i][2 * d2]), lds64(&shwT[n][s][k][2 * d2]), acc);
            float lo, hi; unpack2(acc, lo, hi);
            sc2[n][s ^ g][i][k] = lo + hi;
        }
        __syncthreads();

        // pair MLP 4->6 (SSP) ->8, packed
        float a[6];
        #pragma unroll
        for (int p = 0; p < 3; p++) {
            ull v2 = cB1p[n][p];
            #pragma unroll
            for (int d = 0; d < 4; d++) v2 = fma2(eed[d], cW1p[n][d * 3 + p], v2);
            float lo, hi; unpack2(v2, lo, hi);
            a[2 * p] = ssp_f(lo); a[2 * p + 1] = ssp_f(hi);
        }
        ull acc[4];
        #pragma unroll
        for (int q = 0; q < 4; q++) acc[q] = cB2p[n][q];
        #pragma unroll
        for (int u = 0; u < 6; u++) {
            const ull ad = pack2(a[u], a[u]);
            #pragma unroll
            for (int q = 0; q < 4; q++) acc[q] = fma2(ad, cW2p[n][u * 4 + q], acc[q]);
        }
        #pragma unroll
        for (int q = 0; q < 4; q++) {
            const ull coef = mul2(lds64(&sc2[n][g][lane][2 * q]), mask2);
            acc[q] = mul2(acc[q], coef);
        }

        // fold-reduce over j (b64 value folding)
        {
            const bool h16 = (lane & 16), h8 = (lane & 8);
            ull s;
            #pragma unroll
            for (int q = 0; q < 2; q++) {
                s = __shfl_xor_sync(M, h16 ? acc[q] : acc[q + 2], 16);
                acc[q] = add2(h16 ? acc[q + 2] : acc[q], s);
            }
            s = __shfl_xor_sync(M, h8 ? acc[0] : acc[1], 8);
            acc[0] = add2(h8 ? acc[1] : acc[0], s);
            acc[0] = add2(acc[0], __shfl_xor_sync(M, acc[0], 4));
            acc[0] = add2(acc[0], __shfl_xor_sync(M, acc[0], 2));
            acc[0] = add2(acc[0], __shfl_xor_sync(M, acc[0], 1));
        }
        // add nuclear message (packed), gather z pairs to all lanes
        acc[0] = add2(acc[0], lds64(&sznuc[n][i][2 * qcls]));
        ull z2[4];
        #pragma unroll
        for (int q = 0; q < 4; q++)
            z2[q] = __shfl_sync(M, acc[0], ((q >> 1) << 4) | ((q & 1) << 3));

        // residual update: x += z @ g_w + g_b  (lanes 0..15, one dim each; warp-local)
        if (lane < 16) {
            ull d2 = pack2(sgb[n][lane], 0.f);
            #pragma unroll
            for (int q = 0; q < 4; q++)
                d2 = fma2(z2[q], lds64(&sgwT[n][lane][2 * q]), d2);
            float lo, hi; unpack2(d2, lo, hi);
            sx[i][lane] += lo + hi;
        }
        __syncwarp();
    }
    __syncthreads();

    // ---- orbital projection + sum over electrons ----
    if (i < 16) {
        float v = sx[tid >> 4][tid & 15] * sorb[tid & 15];
        v += __shfl_xor_sync(M, v, 16);
        v += __shfl_xor_sync(M, v, 8);
        v += __shfl_xor_sync(M, v, 4);
        v += __shfl_xor_sync(M, v, 2);
        v += __shfl_xor_sync(M, v, 1);
        if (lane == 0) spart[i] = v;
    }
    __syncthreads();
    if (tid == 0) {
        float s = 0.f;
        #pragma unroll
        for (int w = 0; w < 16; w++) s += spart[w];
        out[b] = s;
    }
}

extern "C" void kernel_launch(void* const* d_in, const int* in_sizes, int n_in,
                              void* d_out, int out_size)
{
    const float* dn   = (const float*)d_in[0];
    const float* de   = (const float*)d_in[1];
    const float* Xe   = (const float*)d_in[2];
    const float* Yn   = (const float*)d_in[3];
    const float* hsw  = (const float*)d_in[8];
    const float* hsb  = (const float*)d_in[9];
    const float* haw  = (const float*)d_in[10];
    const float* hab  = (const float*)d_in[11];
    const float* gw   = (const float*)d_in[12];
    const float* gb   = (const float*)d_in[13];
    const float* orb  = (const float*)d_in[14];
    float* out = (float*)d_out;

    // packed constant views share bytes with the original row-major tensors
    cudaMemcpyToSymbolAsync(cW1p, d_in[4], 48 * sizeof(float), 0, cudaMemcpyDeviceToDevice, 0);
    cudaMemcpyToSymbolAsync(cB1p, d_in[5], 12 * sizeof(float), 0, cudaMemcpyDeviceToDevice, 0);
    cudaMemcpyToSymbolAsync(cW2p, d_in[6], 96 * sizeof(float), 0, cudaMemcpyDeviceToDevice, 0);
    cudaMemcpyToSymbolAsync(cB2p, d_in[7], 16 * sizeof(float), 0, cudaMemcpyDeviceToDevice, 0);

    const int B = in_sizes[0] / (NE * NA * 4);   // dists_nuc: (B,32,8,4)

    dim3 blk(32, 32);
    omni_kernel<<<B, blk>>>(dn, de, Xe, Yn,
                            hsw, hsb, haw, hab, gw, gb, orb, out);
}

// round 4
// speedup vs baseline: 2.4854x; 1.0649x over previous
#include <cuda_runtime.h>

#define LN2 0.69314718055994531f
typedef unsigned long long ull;

// Warp-uniform weights in constant bank (pairs contiguous in the original tensors)
__constant__ ull cW1p[2][12];   // [n][d*3 + upair]
__constant__ ull cB1p[2][3];
__constant__ ull cW2p[2][24];   // [n][u*4 + kpair]
__constant__ ull cB2p[2][4];

__device__ __forceinline__ ull fma2(ull a, ull b, ull c) {
    ull d; asm("fma.rn.f32x2 %0,%1,%2,%3;" : "=l"(d) : "l"(a), "l"(b), "l"(c)); return d;
}
__device__ __forceinline__ ull mul2(ull a, ull b) {
    ull d; asm("mul.rn.f32x2 %0,%1,%2;" : "=l"(d) : "l"(a), "l"(b)); return d;
}
__device__ __forceinline__ ull add2(ull a, ull b) {
    ull d; asm("add.rn.f32x2 %0,%1,%2;" : "=l"(d) : "l"(a), "l"(b)); return d;
}
__device__ __forceinline__ ull pack2(float lo, float hi) {
    ull d; asm("mov.b64 %0,{%1,%2};" : "=l"(d) : "f"(lo), "f"(hi)); return d;
}
__device__ __forceinline__ void unpack2(ull v, float& lo, float& hi) {
    asm("mov.b64 {%0,%1},%2;" : "=f"(lo), "=f"(hi) : "l"(v));
}
__device__ __forceinline__ ull lds64(const float* p) {
    return *reinterpret_cast<const ull*>(p);
}
__device__ __forceinline__ float ssp_f(float v) {
    // softplus(v) - ln2 = ln2*(log2(1 + e^v) - 1)
    return fmaf(__log2f(1.0f + __expf(v)), LN2, -LN2);
}

__global__ __launch_bounds__(256, 2)
void omni_kernel(const float* __restrict__ dn, const float* __restrict__ de,
                 const float* __restrict__ Xe, const float* __restrict__ Yn,
                 const float* __restrict__ hsw, const float* __restrict__ hsb,
                 const float* __restrict__ haw, const float* __restrict__ hab,
                 const float* __restrict__ gw, const float* __restrict__ gb,
                 const float* __restrict__ orb, float* __restrict__ out)
{
    const int b    = blockIdx.x;
    const int lane = threadIdx.x;        // partner electron j
    const int w    = threadIdx.y;        // 0..7; warp w owns i = w + 8r, r=0..3
    const int tid  = (w << 5) | lane;
    const unsigned M = 0xffffffffu;

    __shared__ float shwT[2][2][8][18];  // [n][s][k][d] pairs (72B stride, conflict-free)
    __shared__ float shb[2][2][8];
    __shared__ float sgwT[2][16][10];    // [n][t][k] pairs (40B stride)
    __shared__ float sgb[2][16];
    __shared__ float sY[64];             // [m*8+k]
    __shared__ float sorb[16];
    __shared__ float sx[32][16];         // embeddings
    __shared__ float sc2[2][2][32][10];  // [n][spin][j][k] pairs
    __shared__ float sznuc[2][32][8];
    __shared__ float spart[8];

    // ---- stage lane-indexed weights ----
    #pragma unroll
    for (int t = tid; t < 512; t += 256) {
        const int n = t >> 8, r0 = t & 255, s = r0 >> 7, r2 = r0 & 127, k = r2 >> 4, d = r2 & 15;
        shwT[n][s][k][d] = (s ? haw : hsw)[n * 128 + d * 8 + k];
    }
    {
        const int n = tid >> 7, r0 = tid & 127, t = r0 >> 3, k = r0 & 7;
        sgwT[n][t][k] = gw[n * 128 + k * 16 + t];
    }
    if (tid < 16) { const int n = tid >> 3, k = tid & 7; shb[n][0][k] = hsb[tid]; shb[n][1][k] = hab[tid]; }
    if (tid < 32) ((float*)sgb)[tid] = gb[tid];
    if (tid < 64) sY[tid]   = Yn[tid];
    if (tid < 16) sorb[tid] = orb[tid];
    #pragma unroll
    for (int t = tid; t < 512; t += 256) sx[t >> 4][t & 15] = Xe[t & 15];

    // pair distance features for 4 i's (kept across both interactions)
    float4 ee[4];
    #pragma unroll
    for (int r = 0; r < 4; r++)
        ee[r] = *reinterpret_cast<const float4*>(
            &de[(((size_t)b * 32 + (w + 8 * r)) * 32 + lane) << 2]);
    __syncthreads();

    // ---- nuclear messages: en is n-independent, load once; 2-way ILP over n ----
    {
        const int ii = tid >> 3, m = tid & 7;
        const float4 en = *reinterpret_cast<const float4*>(
            &dn[(((size_t)b * 32 + ii) * 8 + m) << 2]);
        const ull e0 = pack2(en.x, en.x), e1 = pack2(en.y, en.y),
                  e2 = pack2(en.z, en.z), e3 = pack2(en.w, en.w);
        ull sy[4];
        #pragma unroll
        for (int q = 0; q < 4; q++) sy[q] = lds64(&sY[m * 8 + 2 * q]);
        const bool h4 = (m & 4), h2 = (m & 2);
        const int qc = (m >> 1) & 3;
        #pragma unroll
        for (int n = 0; n < 2; n++) {
            float a[6];
            #pragma unroll
            for (int p = 0; p < 3; p++) {
                ull v2 = cB1p[n][p];
                v2 = fma2(e0, cW1p[n][p],     v2);
                v2 = fma2(e1, cW1p[n][3 + p], v2);
                v2 = fma2(e2, cW1p[n][6 + p], v2);
                v2 = fma2(e3, cW1p[n][9 + p], v2);
                float lo, hi; unpack2(v2, lo, hi);
                a[2 * p] = ssp_f(lo); a[2 * p + 1] = ssp_f(hi);
            }
            ull A[4];
            #pragma unroll
            for (int q = 0; q < 4; q++) A[q] = cB2p[n][q];
            #pragma unroll
            for (int u = 0; u < 6; u++) {
                const ull ad = pack2(a[u], a[u]);
                #pragma unroll
                for (int q = 0; q < 4; q++) A[q] = fma2(ad, cW2p[n][u * 4 + q], A[q]);
            }
            #pragma unroll
            for (int q = 0; q < 4; q++) A[q] = mul2(A[q], sy[q]);
            ull s;
            #pragma unroll
            for (int q = 0; q < 2; q++) {
                s = __shfl_xor_sync(M, h4 ? A[q] : A[q + 2], 4);
                A[q] = add2(h4 ? A[q + 2] : A[q], s);
            }
            s = __shfl_xor_sync(M, h2 ? A[0] : A[1], 2);
            A[0] = add2(h2 ? A[1] : A[0], s);
            A[0] = add2(A[0], __shfl_xor_sync(M, A[0], 1));
            if ((m & 1) == 0)
                *reinterpret_cast<ull*>(&sznuc[n][ii][2 * qc]) = A[0];
        }
    }
    __syncthreads();

    const int sH    = (lane >> 3) & 1;   // h-feature spin slot
    const int kH    = lane & 7;
    const int rbase = (lane >> 4) << 1;  // lanes<16: r=0,1 ; lanes>=16: r=2,3
    const int lt    = lane & 15;
    const int qcls  = (lane >> 3) & 3;

    #pragma unroll
    for (int n = 0; n < 2; n++) {
        // ---- h features: all 32 lanes busy, halves cover r-pairs ----
        {
            ull wh[8];
            #pragma unroll
            for (int d2 = 0; d2 < 8; d2++) wh[d2] = lds64(&shwT[n][sH][kH][2 * d2]);
            const float bb = shb[n][sH][kH];
            #pragma unroll
            for (int rr = 0; rr < 2; rr++) {
                const int r = rbase + rr;
                const int i = w + 8 * r;
                ull acc = pack2(bb, 0.f);
                #pragma unroll
                for (int d2 = 0; d2 < 8; d2++)
                    acc = fma2(lds64(&sx[i][2 * d2]), wh[d2], acc);
                float lo, hi; unpack2(acc, lo, hi);
                sc2[n][sH ^ (r >> 1)][i][kH] = lo + hi;
            }
        }
        __syncthreads();

        // coef rows depend only on spin: 2 loads serve all 4 i's
        ull coef[2][4];
        #pragma unroll
        for (int gg = 0; gg < 2; gg++)
            #pragma unroll
            for (int q = 0; q < 4; q++) coef[gg][q] = lds64(&sc2[n][gg][lane][2 * q]);

        ull gwr[4];
        #pragma unroll
        for (int q = 0; q < 4; q++) gwr[q] = lds64(&sgwT[n][lt][2 * q]);
        const float gbb = sgb[n][lt];

        // ---- 4 independent pair-MLP + fold chains ----
        ull zred[4];
        #pragma unroll
        for (int r = 0; r < 4; r++) {
            const ull e0 = pack2(ee[r].x, ee[r].x), e1 = pack2(ee[r].y, ee[r].y),
                      e2 = pack2(ee[r].z, ee[r].z), e3 = pack2(ee[r].w, ee[r].w);
            float a[6];
            #pragma unroll
            for (int p = 0; p < 3; p++) {
                ull v2 = cB1p[n][p];
                v2 = fma2(e0, cW1p[n][p],     v2);
                v2 = fma2(e1, cW1p[n][3 + p], v2);
                v2 = fma2(e2, cW1p[n][6 + p], v2);
                v2 = fma2(e3, cW1p[n][9 + p], v2);
                float lo, hi; unpack2(v2, lo, hi);
                a[2 * p] = ssp_f(lo); a[2 * p + 1] = ssp_f(hi);
            }
            ull A[4];
            #pragma unroll
            for (int q = 0; q < 4; q++) A[q] = cB2p[n][q];
            #pragma unroll
            for (int u = 0; u < 6; u++) {
                const ull ad = pack2(a[u], a[u]);
                #pragma unroll
                for (int q = 0; q < 4; q++) A[q] = fma2(ad, cW2p[n][u * 4 + q], A[q]);
            }
            const int gr = r >> 1;
            #pragma unroll
            for (int q = 0; q < 4; q++) A[q] = mul2(A[q], coef[gr][q]);
            if (lane == w + 8 * r) { A[0] = 0; A[1] = 0; A[2] = 0; A[3] = 0; }  // self-mask

            const bool h16 = (lane & 16), h8 = (lane & 8);
            ull s;
            #pragma unroll
            for (int q = 0; q < 2; q++) {
                s = __shfl_xor_sync(M, h16 ? A[q] : A[q + 2], 16);
                A[q] = add2(h16 ? A[q + 2] : A[q], s);
            }
            s = __shfl_xor_sync(M, h8 ? A[0] : A[1], 8);
            A[0] = add2(h8 ? A[1] : A[0], s);
            A[0] = add2(A[0], __shfl_xor_sync(M, A[0], 4));
            A[0] = add2(A[0], __shfl_xor_sync(M, A[0], 2));
            A[0] = add2(A[0], __shfl_xor_sync(M, A[0], 1));
            zred[r] = add2(A[0], lds64(&sznuc[n][w + 8 * r][2 * qcls]));
        }

        // ---- gather z pairs + residual update (halves split the r's) ----
        #pragma unroll
        for (int r = 0; r < 4; r++) {
            const ull z0 = __shfl_sync(M, zred[r], 0);
            const ull z1 = __shfl_sync(M, zred[r], 8);
            const ull z2 = __shfl_sync(M, zred[r], 16);
            const ull z3 = __shfl_sync(M, zred[r], 24);
            if ((r >> 1) == (lane >> 4)) {
                ull d2 = pack2(gbb, 0.f);
                d2 = fma2(z0, gwr[0], d2);
                d2 = fma2(z1, gwr[1], d2);
                d2 = fma2(z2, gwr[2], d2);
                d2 = fma2(z3, gwr[3], d2);
                float lo, hi; unpack2(d2, lo, hi);
                sx[w + 8 * r][lt] += lo + hi;   // warp-local rows
            }
        }
        __syncwarp();
    }
    __syncthreads();

    // ---- orbital projection + sum over electrons ----
    float v = 0.f;
    #pragma unroll
    for (int t = tid; t < 512; t += 256)
        v += sx[t >> 4][t & 15] * sorb[t & 15];
    v += __shfl_xor_sync(M, v, 16);
    v += __shfl_xor_sync(M, v, 8);
    v += __shfl_xor_sync(M, v, 4);
    v += __shfl_xor_sync(M, v, 2);
    v += __shfl_xor_sync(M, v, 1);
    if (lane == 0) spart[w] = v;
    __syncthreads();
    if (tid == 0) {
        float s2 = 0.f;
        #pragma unroll
        for (int q = 0; q < 8; q++) s2 += spart[q];
        out[b] = s2;
    }
}

extern "C" void kernel_launch(void* const* d_in, const int* in_sizes, int n_in,
                              void* d_out, int out_size)
{
    const float* dn   = (const float*)d_in[0];
    const float* de   = (const float*)d_in[1];
    const float* Xe   = (const float*)d_in[2];
    const float* Yn   = (const float*)d_in[3];
    const float* hsw  = (const float*)d_in[8];
    const float* hsb  = (const float*)d_in[9];
    const float* haw  = (const float*)d_in[10];
    const float* hab  = (const float*)d_in[11];
    const float* gw   = (const float*)d_in[12];
    const float* gb   = (const float*)d_in[13];
    const float* orb  = (const float*)d_in[14];
    float* out = (float*)d_out;

    cudaMemcpyToSymbolAsync(cW1p, d_in[4], 48 * sizeof(float), 0, cudaMemcpyDeviceToDevice, 0);
    cudaMemcpyToSymbolAsync(cB1p, d_in[5], 12 * sizeof(float), 0, cudaMemcpyDeviceToDevice, 0);
    cudaMemcpyToSymbolAsync(cW2p, d_in[6], 96 * sizeof(float), 0, cudaMemcpyDeviceToDevice, 0);
    cudaMemcpyToSymbolAsync(cB2p, d_in[7], 16 * sizeof(float), 0, cudaMemcpyDeviceToDevice, 0);

    const int B = in_sizes[0] / (32 * 8 * 4);   // dists_nuc: (B,32,8,4)

    dim3 blk(32, 8);
    omni_kernel<<<B, blk>>>(dn, de, Xe, Yn,
                            hsw, hsb, haw, hab, gw, gb, orb, out);
}

// round 5
// speedup vs baseline: 4.0781x; 1.6408x over previous
#include <cuda_runtime.h>

#define LN2 0.69314718055994531f
typedef unsigned long long ull;

// Warp-uniform weights in constant bank (pairs contiguous in the original tensors)
__constant__ ull cW1p[2][12];   // [n][d*3 + upair]
__constant__ ull cB1p[2][3];
__constant__ ull cW2p[2][24];   // [n][u*4 + kpair]
__constant__ ull cB2p[2][4];

__device__ __forceinline__ ull fma2(ull a, ull b, ull c) {
    ull d; asm("fma.rn.f32x2 %0,%1,%2,%3;" : "=l"(d) : "l"(a), "l"(b), "l"(c)); return d;
}
__device__ __forceinline__ ull mul2(ull a, ull b) {
    ull d; asm("mul.rn.f32x2 %0,%1,%2;" : "=l"(d) : "l"(a), "l"(b)); return d;
}
__device__ __forceinline__ ull add2(ull a, ull b) {
    ull d; asm("add.rn.f32x2 %0,%1,%2;" : "=l"(d) : "l"(a), "l"(b)); return d;
}
__device__ __forceinline__ ull pack2(float lo, float hi) {
    ull d; asm("mov.b64 %0,{%1,%2};" : "=l"(d) : "f"(lo), "f"(hi)); return d;
}
__device__ __forceinline__ void unpack2(ull v, float& lo, float& hi) {
    asm("mov.b64 {%0,%1},%2;" : "=f"(lo), "=f"(hi) : "l"(v));
}
__device__ __forceinline__ ull lds64(const float* p) {
    return *reinterpret_cast<const ull*>(p);
}
__device__ __forceinline__ float ssp_f(float v) {
    // softplus(v) - ln2 = ln2*(log2(1 + e^v) - 1)
    return fmaf(__log2f(1.0f + __expf(v)), LN2, -LN2);
}

// pair MLP 4->6(SSP)->8 for one (i,j), times spin coef, self-masked
__device__ __forceinline__ void pair_mlp(int n, const float4& e, const ull* coefr,
                                         bool selfj, ull* A)
{
    const ull e0 = pack2(e.x, e.x), e1 = pack2(e.y, e.y),
              e2 = pack2(e.z, e.z), e3 = pack2(e.w, e.w);
    float a[6];
    #pragma unroll
    for (int p = 0; p < 3; p++) {
        ull v2 = cB1p[n][p];
        v2 = fma2(e0, cW1p[n][p],     v2);
        v2 = fma2(e1, cW1p[n][3 + p], v2);
        v2 = fma2(e2, cW1p[n][6 + p], v2);
        v2 = fma2(e3, cW1p[n][9 + p], v2);
        float lo, hi; unpack2(v2, lo, hi);
        a[2 * p] = ssp_f(lo); a[2 * p + 1] = ssp_f(hi);
    }
    #pragma unroll
    for (int q = 0; q < 4; q++) A[q] = cB2p[n][q];
    #pragma unroll
    for (int u = 0; u < 6; u++) {
        const ull ad = pack2(a[u], a[u]);
        #pragma unroll
        for (int q = 0; q < 4; q++) A[q] = fma2(ad, cW2p[n][u * 4 + q], A[q]);
    }
    #pragma unroll
    for (int q = 0; q < 4; q++) A[q] = selfj ? 0ull : mul2(A[q], coefr[q]);
}

__global__ __launch_bounds__(256, 2)
void omni_kernel(const float* __restrict__ dn, const float* __restrict__ de,
                 const float* __restrict__ Xe, const float* __restrict__ Yn,
                 const float* __restrict__ hsw, const float* __restrict__ hsb,
                 const float* __restrict__ haw, const float* __restrict__ hab,
                 const float* __restrict__ gw, const float* __restrict__ gb,
                 const float* __restrict__ orb, float* __restrict__ out)
{
    const int b    = blockIdx.x;
    const int lane = threadIdx.x;        // partner electron j
    const int w    = threadIdx.y;        // warp w owns i = w + 8r, r=0..3
    const int tid  = (w << 5) | lane;
    const unsigned M = 0xffffffffu;

    __shared__ float shwT[2][2][8][18];  // [n][s][k][d] pairs (72B stride)
    __shared__ float shb[2][2][8];
    __shared__ float sgwT[2][16][10];    // [n][t][k] pairs (40B stride)
    __shared__ float sgb[2][16];
    __shared__ float sY[64];             // [m*8+k]
    __shared__ float sorb[16];
    __shared__ float sx[32][16];         // embeddings
    __shared__ float sc2[2][2][32][10];  // [n][spin][j][k] pairs
    __shared__ float sznuc[2][32][8];
    __shared__ float szr[8][4][8];       // per-warp z buffer [w][r][k]
    __shared__ float spart[8];

    // ---- stage lane-indexed weights ----
    #pragma unroll
    for (int t = tid; t < 512; t += 256) {
        const int n = t >> 8, r0 = t & 255, s = r0 >> 7, r2 = r0 & 127, k = r2 >> 4, d = r2 & 15;
        shwT[n][s][k][d] = (s ? haw : hsw)[n * 128 + d * 8 + k];
    }
    {
        const int n = tid >> 7, r0 = tid & 127, t = r0 >> 3, k = r0 & 7;
        sgwT[n][t][k] = gw[n * 128 + k * 16 + t];
    }
    if (tid < 16) { const int n = tid >> 3, k = tid & 7; shb[n][0][k] = hsb[tid]; shb[n][1][k] = hab[tid]; }
    if (tid < 32) ((float*)sgb)[tid] = gb[tid];
    if (tid < 64) sY[tid]   = Yn[tid];
    if (tid < 16) sorb[tid] = orb[tid];
    #pragma unroll
    for (int t = tid; t < 512; t += 256) sx[t >> 4][t & 15] = Xe[t & 15];

    // pair distance features for 4 i's
    float4 ee[4];
    #pragma unroll
    for (int r = 0; r < 4; r++)
        ee[r] = *reinterpret_cast<const float4*>(
            &de[(((size_t)b * 32 + (w + 8 * r)) * 32 + lane) << 2]);
    __syncthreads();

    // ---- nuclear messages: en loaded once for both interactions ----
    {
        const int ii = tid >> 3, m = tid & 7;
        const float4 en = *reinterpret_cast<const float4*>(
            &dn[(((size_t)b * 32 + ii) * 8 + m) << 2]);
        const ull e0 = pack2(en.x, en.x), e1 = pack2(en.y, en.y),
                  e2 = pack2(en.z, en.z), e3 = pack2(en.w, en.w);
        ull sy[4];
        #pragma unroll
        for (int q = 0; q < 4; q++) sy[q] = lds64(&sY[m * 8 + 2 * q]);
        const bool h4 = (m & 4), h2 = (m & 2);
        const int qc = (m >> 1) & 3;
        #pragma unroll
        for (int n = 0; n < 2; n++) {
            float a[6];
            #pragma unroll
            for (int p = 0; p < 3; p++) {
                ull v2 = cB1p[n][p];
                v2 = fma2(e0, cW1p[n][p],     v2);
                v2 = fma2(e1, cW1p[n][3 + p], v2);
                v2 = fma2(e2, cW1p[n][6 + p], v2);
                v2 = fma2(e3, cW1p[n][9 + p], v2);
                float lo, hi; unpack2(v2, lo, hi);
                a[2 * p] = ssp_f(lo); a[2 * p + 1] = ssp_f(hi);
            }
            ull A[4];
            #pragma unroll
            for (int q = 0; q < 4; q++) A[q] = cB2p[n][q];
            #pragma unroll
            for (int u = 0; u < 6; u++) {
                const ull ad = pack2(a[u], a[u]);
                #pragma unroll
                for (int q = 0; q < 4; q++) A[q] = fma2(ad, cW2p[n][u * 4 + q], A[q]);
            }
            #pragma unroll
            for (int q = 0; q < 4; q++) A[q] = mul2(A[q], sy[q]);
            ull s;
            #pragma unroll
            for (int q = 0; q < 2; q++) {
                s = __shfl_xor_sync(M, h4 ? A[q] : A[q + 2], 4);
                A[q] = add2(h4 ? A[q + 2] : A[q], s);
            }
            s = __shfl_xor_sync(M, h2 ? A[0] : A[1], 2);
            A[0] = add2(h2 ? A[1] : A[0], s);
            A[0] = add2(A[0], __shfl_xor_sync(M, A[0], 1));
            if ((m & 1) == 0)
                *reinterpret_cast<ull*>(&sznuc[n][ii][2 * qc]) = A[0];
        }
    }
    __syncthreads();

    const int  sH    = (lane >> 3) & 1;
    const int  kH    = lane & 7;
    const int  rbase = (lane >> 4) << 1;
    const int  lt    = lane & 15;
    const bool b4 = (lane & 16), b3 = (lane & 8), b2 = (lane & 4), b1 = (lane & 2);
    const int  r_sel = ((lane >> 3) & 2) | ((lane >> 3) & 1);   // 2*b4 + b3
    const int  q_sel = (lane >> 1) & 3;                         // 2*b2 + b1

    #pragma unroll
    for (int n = 0; n < 2; n++) {
        // ---- h features (all 32 lanes busy) ----
        {
            ull wh[8];
            #pragma unroll
            for (int d2 = 0; d2 < 8; d2++) wh[d2] = lds64(&shwT[n][sH][kH][2 * d2]);
            const float bb = shb[n][sH][kH];
            #pragma unroll
            for (int rr = 0; rr < 2; rr++) {
                const int r = rbase + rr;
                const int i = w + 8 * r;
                ull acc = pack2(bb, 0.f);
                #pragma unroll
                for (int d2 = 0; d2 < 8; d2++)
                    acc = fma2(lds64(&sx[i][2 * d2]), wh[d2], acc);
                float lo, hi; unpack2(acc, lo, hi);
                sc2[n][sH ^ (r >> 1)][i][kH] = lo + hi;
            }
        }
        __syncthreads();

        // coef rows depend only on spin group
        ull coef[2][4];
        #pragma unroll
        for (int gg = 0; gg < 2; gg++)
            #pragma unroll
            for (int q = 0; q < 4; q++) coef[gg][q] = lds64(&sc2[n][gg][lane][2 * q]);

        ull gwr[4];
        #pragma unroll
        for (int q = 0; q < 4; q++) gwr[q] = lds64(&sgwT[n][lt][2 * q]);
        const float gbb = sgb[n][lt];

        // ---- combined fold: 16 values (4r x 4q) over 5 rounds ----
        ull F0[4], F1[4], Z;
        {   // stage 1: r=0 and r=2, fold over xor16 (keeps r = 2*b4)
            ull A0[4], A2[4];
            pair_mlp(n, ee[0], coef[0], lane == w,      A0);
            pair_mlp(n, ee[2], coef[1], lane == w + 16, A2);
            #pragma unroll
            for (int q = 0; q < 4; q++) {
                const ull s = __shfl_xor_sync(M, b4 ? A0[q] : A2[q], 16);
                F0[q] = add2(b4 ? A2[q] : A0[q], s);
            }
        }
        {   // stage 2: r=1 and r=3 (keeps r = 2*b4 + 1)
            ull A1[4], A3[4];
            pair_mlp(n, ee[1], coef[0], lane == w + 8,  A1);
            pair_mlp(n, ee[3], coef[1], lane == w + 24, A3);
            #pragma unroll
            for (int q = 0; q < 4; q++) {
                const ull s = __shfl_xor_sync(M, b4 ? A1[q] : A3[q], 16);
                F1[q] = add2(b4 ? A3[q] : A1[q], s);
            }
        }
        // round 2 (xor8): r-bit0 = b3
        #pragma unroll
        for (int q = 0; q < 4; q++) {
            const ull s = __shfl_xor_sync(M, b3 ? F0[q] : F1[q], 8);
            F0[q] = add2(b3 ? F1[q] : F0[q], s);
        }
        // round 3 (xor4): q-bit1 = b2
        {
            ull s = __shfl_xor_sync(M, b2 ? F0[0] : F0[2], 4);
            F0[0] = add2(b2 ? F0[2] : F0[0], s);
            s = __shfl_xor_sync(M, b2 ? F0[1] : F0[3], 4);
            F0[1] = add2(b2 ? F0[3] : F0[1], s);
        }
        // round 4 (xor2): q-bit0 = b1 ; round 5 (xor1): butterfly
        {
            ull s = __shfl_xor_sync(M, b1 ? F0[0] : F0[1], 2);
            Z = add2(b1 ? F0[1] : F0[0], s);
            Z = add2(Z, __shfl_xor_sync(M, Z, 1));
        }
        // add nuclear message, publish z(r_sel, q_sel) to per-warp buffer
        Z = add2(Z, lds64(&sznuc[n][w + 8 * r_sel][2 * q_sel]));
        if ((lane & 1) == 0)
            *reinterpret_cast<ull*>(&szr[w][r_sel][2 * q_sel]) = Z;
        __syncwarp();

        // ---- residual update: halves split the r's, one dim t per lane ----
        #pragma unroll
        for (int rr = 0; rr < 2; rr++) {
            const int r = rbase + rr;
            ull d2 = pack2(gbb, 0.f);
            #pragma unroll
            for (int q = 0; q < 4; q++)
                d2 = fma2(lds64(&szr[w][r][2 * q]), gwr[q], d2);
            float lo, hi; unpack2(d2, lo, hi);
            sx[w + 8 * r][lt] += lo + hi;
        }
        __syncwarp();
    }
    __syncthreads();

    // ---- orbital projection + sum over electrons ----
    float v = 0.f;
    #pragma unroll
    for (int t = tid; t < 512; t += 256)
        v += sx[t >> 4][t & 15] * sorb[t & 15];
    v += __shfl_xor_sync(M, v, 16);
    v += __shfl_xor_sync(M, v, 8);
    v += __shfl_xor_sync(M, v, 4);
    v += __shfl_xor_sync(M, v, 2);
    v += __shfl_xor_sync(M, v, 1);
    if (lane == 0) spart[w] = v;
    __syncthreads();
    if (tid == 0) {
        float s2 = 0.f;
        #pragma unroll
        for (int q = 0; q < 8; q++) s2 += spart[q];
        out[b] = s2;
    }
}

extern "C" void kernel_launch(void* const* d_in, const int* in_sizes, int n_in,
                              void* d_out, int out_size)
{
    const float* dn   = (const float*)d_in[0];
    const float* de   = (const float*)d_in[1];
    const float* Xe   = (const float*)d_in[2];
    const float* Yn   = (const float*)d_in[3];
    const float* hsw  = (const float*)d_in[8];
    const float* hsb  = (const float*)d_in[9];
    const float* haw  = (const float*)d_in[10];
    const float* hab  = (const float*)d_in[11];
    const float* gw   = (const float*)d_in[12];
    const float* gb   = (const float*)d_in[13];
    const float* orb  = (const float*)d_in[14];
    float* out = (float*)d_out;

    cudaMemcpyToSymbolAsync(cW1p, d_in[4], 48 * sizeof(float), 0, cudaMemcpyDeviceToDevice, 0);
    cudaMemcpyToSymbolAsync(cB1p, d_in[5], 12 * sizeof(float), 0, cudaMemcpyDeviceToDevice, 0);
    cudaMemcpyToSymbolAsync(cW2p, d_in[6], 96 * sizeof(float), 0, cudaMemcpyDeviceToDevice, 0);
    cudaMemcpyToSymbolAsync(cB2p, d_in[7], 16 * sizeof(float), 0, cudaMemcpyDeviceToDevice, 0);

    const int B = in_sizes[0] / (32 * 8 * 4);   // dists_nuc: (B,32,8,4)

    dim3 blk(32, 8);
    omni_kernel<<<B, blk>>>(dn, de, Xe, Yn,
                            hsw, hsb, haw, hab, gw, gb, orb, out);
}

// round 6
// speedup vs baseline: 4.4085x; 1.0810x over previous
#include <cuda_runtime.h>

#define LN2  0.69314718055994531f
#define L2E  1.4426950408889634f
typedef unsigned long long ull;

// Transformed warp-uniform weights in constant bank:
//   cW1p/cB1p pre-scaled by log2(e)  (layer-1 output directly in log2 domain)
//   cW2p pre-scaled by ln2, cB2p absorbs -ln2*colsum(W2) (softplus affine folded)
__constant__ ull cW1p[2][12];   // [n][d*3 + upair]
__constant__ ull cB1p[2][3];
__constant__ ull cW2p[2][24];   // [n][u*4 + kpair]
__constant__ ull cB2p[2][4];

__device__ float d_wscratch[172];   // 48 W1' | 12 B1' | 96 W2' | 16 B2'

__global__ void prep_kernel(const float* __restrict__ w1, const float* __restrict__ wb1,
                            const float* __restrict__ w2, const float* __restrict__ wb2)
{
    const int t = threadIdx.x;
    if (t < 48) d_wscratch[t]      = w1[t]  * L2E;
    if (t < 12) d_wscratch[48 + t] = wb1[t] * L2E;
    if (t < 96) d_wscratch[60 + t] = w2[t]  * LN2;
    if (t < 16) {
        const int n = t >> 3, k = t & 7;
        float s = 0.f;
        #pragma unroll
        for (int u = 0; u < 6; u++) s += w2[n * 48 + u * 8 + k];
        d_wscratch[156 + t] = wb2[t] - LN2 * s;
    }
}

__device__ __forceinline__ ull fma2(ull a, ull b, ull c) {
    ull d; asm("fma.rn.f32x2 %0,%1,%2,%3;" : "=l"(d) : "l"(a), "l"(b), "l"(c)); return d;
}
__device__ __forceinline__ ull mul2(ull a, ull b) {
    ull d; asm("mul.rn.f32x2 %0,%1,%2;" : "=l"(d) : "l"(a), "l"(b)); return d;
}
__device__ __forceinline__ ull add2(ull a, ull b) {
    ull d; asm("add.rn.f32x2 %0,%1,%2;" : "=l"(d) : "l"(a), "l"(b)); return d;
}
__device__ __forceinline__ ull pack2(float lo, float hi) {
    ull d; asm("mov.b64 %0,{%1,%2};" : "=l"(d) : "f"(lo), "f"(hi)); return d;
}
__device__ __forceinline__ void unpack2(ull v, float& lo, float& hi) {
    asm("mov.b64 {%0,%1},%2;" : "=f"(lo), "=f"(hi) : "l"(v));
}
__device__ __forceinline__ ull lds64(const float* p) {
    return *reinterpret_cast<const ull*>(p);
}
// log2(1 + 2^t): EX2 -> FADD -> LG2 (softplus with affine folded into weights)
__device__ __forceinline__ float lg1p2(float t) {
    float e, r;
    asm("ex2.approx.f32 %0, %1;" : "=f"(e) : "f"(t));
    asm("lg2.approx.f32 %0, %1;" : "=f"(r) : "f"(1.0f + e));
    return r;
}

// pair MLP 4->6(lg-SSP)->8 for one (i,j), times spin coef, times self-mask
__device__ __forceinline__ void pair_mlp(int n, const float4& e, const ull* coefr,
                                         ull m2, ull* A)
{
    const ull e0 = pack2(e.x, e.x), e1 = pack2(e.y, e.y),
              e2 = pack2(e.z, e.z), e3 = pack2(e.w, e.w);
    float a[6];
    #pragma unroll
    for (int p = 0; p < 3; p++) {
        ull v2 = cB1p[n][p];
        v2 = fma2(e0, cW1p[n][p],     v2);
        v2 = fma2(e1, cW1p[n][3 + p], v2);
        v2 = fma2(e2, cW1p[n][6 + p], v2);
        v2 = fma2(e3, cW1p[n][9 + p], v2);
        float lo, hi; unpack2(v2, lo, hi);
        a[2 * p] = lg1p2(lo); a[2 * p + 1] = lg1p2(hi);
    }
    #pragma unroll
    for (int q = 0; q < 4; q++) A[q] = cB2p[n][q];
    #pragma unroll
    for (int u = 0; u < 6; u++) {
        const ull ad = pack2(a[u], a[u]);
        #pragma unroll
        for (int q = 0; q < 4; q++) A[q] = fma2(ad, cW2p[n][u * 4 + q], A[q]);
    }
    #pragma unroll
    for (int q = 0; q < 4; q++) A[q] = mul2(mul2(A[q], coefr[q]), m2);
}

__global__ __launch_bounds__(256, 2)
void omni_kernel(const float* __restrict__ dn, const float* __restrict__ de,
                 const float* __restrict__ Xe, const float* __restrict__ Yn,
                 const float* __restrict__ hsw, const float* __restrict__ hsb,
                 const float* __restrict__ haw, const float* __restrict__ hab,
                 const float* __restrict__ gw, const float* __restrict__ gb,
                 const float* __restrict__ orb, float* __restrict__ out)
{
    const int b    = blockIdx.x;
    const int lane = threadIdx.x;        // partner electron j
    const int w    = threadIdx.y;        // warp w owns i = w + 8r, r=0..3
    const int tid  = (w << 5) | lane;
    const unsigned M = 0xffffffffu;

    __shared__ float shwT[2][2][8][18];  // [n][s][k][d] pairs (72B stride)
    __shared__ float shb[2][2][8];
    __shared__ float sgwT[2][16][10];    // [n][t][k] pairs (40B stride)
    __shared__ float sgb[2][16];
    __shared__ float sY[64];             // [m*8+k]
    __shared__ float sorb[16];
    __shared__ float sx[32][16];         // embeddings
    __shared__ float sc2[2][2][32][10];  // [n][spin][j][k] pairs
    __shared__ float sznuc[2][32][8];
    __shared__ float szr[8][4][8];       // per-warp z buffer [w][r][k]
    __shared__ float spart[8];

    // ---- stage lane-indexed weights ----
    #pragma unroll
    for (int t = tid; t < 512; t += 256) {
        const int n = t >> 8, r0 = t & 255, s = r0 >> 7, r2 = r0 & 127, k = r2 >> 4, d = r2 & 15;
        shwT[n][s][k][d] = (s ? haw : hsw)[n * 128 + d * 8 + k];
    }
    {
        const int n = tid >> 7, r0 = tid & 127, t = r0 >> 3, k = r0 & 7;
        sgwT[n][t][k] = gw[n * 128 + k * 16 + t];
    }
    if (tid < 16) { const int n = tid >> 3, k = tid & 7; shb[n][0][k] = hsb[tid]; shb[n][1][k] = hab[tid]; }
    if (tid < 32) ((float*)sgb)[tid] = gb[tid];
    if (tid < 64) sY[tid]   = Yn[tid];
    if (tid < 16) sorb[tid] = orb[tid];
    #pragma unroll
    for (int t = tid; t < 512; t += 256) sx[t >> 4][t & 15] = Xe[t & 15];

    // pair distance features for 4 i's
    float4 ee[4];
    #pragma unroll
    for (int r = 0; r < 4; r++)
        ee[r] = *reinterpret_cast<const float4*>(
            &de[(((size_t)b * 32 + (w + 8 * r)) * 32 + lane) << 2]);
    __syncthreads();

    // ---- nuclear messages: en loaded once for both interactions ----
    {
        const int ii = tid >> 3, m = tid & 7;
        const float4 en = *reinterpret_cast<const float4*>(
            &dn[(((size_t)b * 32 + ii) * 8 + m) << 2]);
        const ull e0 = pack2(en.x, en.x), e1 = pack2(en.y, en.y),
                  e2 = pack2(en.z, en.z), e3 = pack2(en.w, en.w);
        ull sy[4];
        #pragma unroll
        for (int q = 0; q < 4; q++) sy[q] = lds64(&sY[m * 8 + 2 * q]);
        const bool h4 = (m & 4), h2 = (m & 2);
        const int qc = (m >> 1) & 3;
        #pragma unroll
        for (int n = 0; n < 2; n++) {
            float a[6];
            #pragma unroll
            for (int p = 0; p < 3; p++) {
                ull v2 = cB1p[n][p];
                v2 = fma2(e0, cW1p[n][p],     v2);
                v2 = fma2(e1, cW1p[n][3 + p], v2);
                v2 = fma2(e2, cW1p[n][6 + p], v2);
                v2 = fma2(e3, cW1p[n][9 + p], v2);
                float lo, hi; unpack2(v2, lo, hi);
                a[2 * p] = lg1p2(lo); a[2 * p + 1] = lg1p2(hi);
            }
            ull A[4];
            #pragma unroll
            for (int q = 0; q < 4; q++) A[q] = cB2p[n][q];
            #pragma unroll
            for (int u = 0; u < 6; u++) {
                const ull ad = pack2(a[u], a[u]);
                #pragma unroll
                for (int q = 0; q < 4; q++) A[q] = fma2(ad, cW2p[n][u * 4 + q], A[q]);
            }
            #pragma unroll
            for (int q = 0; q < 4; q++) A[q] = mul2(A[q], sy[q]);
            ull s;
            #pragma unroll
            for (int q = 0; q < 2; q++) {
                s = __shfl_xor_sync(M, h4 ? A[q] : A[q + 2], 4);
                A[q] = add2(h4 ? A[q + 2] : A[q], s);
            }
            s = __shfl_xor_sync(M, h2 ? A[0] : A[1], 2);
            A[0] = add2(h2 ? A[1] : A[0], s);
            A[0] = add2(A[0], __shfl_xor_sync(M, A[0], 1));
            if ((m & 1) == 0)
                *reinterpret_cast<ull*>(&sznuc[n][ii][2 * qc]) = A[0];
        }
    }
    __syncthreads();

    const int  sH    = (lane >> 3) & 1;
    const int  kH    = lane & 7;
    const int  rbase = (lane >> 4) << 1;
    const int  lt    = lane & 15;
    const bool b4 = (lane & 16), b3 = (lane & 8), b2 = (lane & 4), b1 = (lane & 2);
    const int  r_sel = ((lane >> 3) & 2) | ((lane >> 3) & 1);   // 2*b4 + b3
    const int  q_sel = (lane >> 1) & 3;                         // 2*b2 + b1

    // self-mask per r (multiplicative, replaces 64-bit selects)
    ull mk2[4];
    #pragma unroll
    for (int r = 0; r < 4; r++) {
        const float mk = (lane == w + 8 * r) ? 0.f : 1.f;
        mk2[r] = pack2(mk, mk);
    }

    #pragma unroll
    for (int n = 0; n < 2; n++) {
        // ---- h features (all 32 lanes busy) ----
        {
            ull wh[8];
            #pragma unroll
            for (int d2 = 0; d2 < 8; d2++) wh[d2] = lds64(&shwT[n][sH][kH][2 * d2]);
            const float bb = shb[n][sH][kH];
            #pragma unroll
            for (int rr = 0; rr < 2; rr++) {
                const int r = rbase + rr;
                const int i = w + 8 * r;
                ull acc = pack2(bb, 0.f);
                #pragma unroll
                for (int d2 = 0; d2 < 8; d2++)
                    acc = fma2(lds64(&sx[i][2 * d2]), wh[d2], acc);
                float lo, hi; unpack2(acc, lo, hi);
                sc2[n][sH ^ (r >> 1)][i][kH] = lo + hi;
            }
        }
        __syncthreads();

        // coef rows depend only on spin group
        ull coef[2][4];
        #pragma unroll
        for (int gg = 0; gg < 2; gg++)
            #pragma unroll
            for (int q = 0; q < 4; q++) coef[gg][q] = lds64(&sc2[n][gg][lane][2 * q]);

        ull gwr[4];
        #pragma unroll
        for (int q = 0; q < 4; q++) gwr[q] = lds64(&sgwT[n][lt][2 * q]);
        const float gbb = sgb[n][lt];

        // ---- combined fold: 16 values (4r x 4q) over 5 rounds ----
        ull F0[4], F1[4], Z;
        {   // stage 1: r=0 and r=2, fold over xor16 (keeps r = 2*b4)
            ull A0[4], A2[4];
            pair_mlp(n, ee[0], coef[0], mk2[0], A0);
            pair_mlp(n, ee[2], coef[1], mk2[2], A2);
            #pragma unroll
            for (int q = 0; q < 4; q++) {
                const ull s = __shfl_xor_sync(M, b4 ? A0[q] : A2[q], 16);
                F0[q] = add2(b4 ? A2[q] : A0[q], s);
            }
        }
        {   // stage 2: r=1 and r=3 (keeps r = 2*b4 + 1)
            ull A1[4], A3[4];
            pair_mlp(n, ee[1], coef[0], mk2[1], A1);
            pair_mlp(n, ee[3], coef[1], mk2[3], A3);
            #pragma unroll
            for (int q = 0; q < 4; q++) {
                const ull s = __shfl_xor_sync(M, b4 ? A1[q] : A3[q], 16);
                F1[q] = add2(b4 ? A3[q] : A1[q], s);
            }
        }
        // round 2 (xor8): r-bit0 = b3
        #pragma unroll
        for (int q = 0; q < 4; q++) {
            const ull s = __shfl_xor_sync(M, b3 ? F0[q] : F1[q], 8);
            F0[q] = add2(b3 ? F1[q] : F0[q], s);
        }
        // round 3 (xor4): q-bit1 = b2
        {
            ull s = __shfl_xor_sync(M, b2 ? F0[0] : F0[2], 4);
            F0[0] = add2(b2 ? F0[2] : F0[0], s);
            s = __shfl_xor_sync(M, b2 ? F0[1] : F0[3], 4);
            F0[1] = add2(b2 ? F0[3] : F0[1], s);
        }
        // round 4 (xor2): q-bit0 = b1 ; round 5 (xor1): butterfly
        {
            ull s = __shfl_xor_sync(M, b1 ? F0[0] : F0[1], 2);
            Z = add2(b1 ? F0[1] : F0[0], s);
            Z = add2(Z, __shfl_xor_sync(M, Z, 1));
        }
        // add nuclear message, publish z(r_sel, q_sel) to per-warp buffer
        Z = add2(Z, lds64(&sznuc[n][w + 8 * r_sel][2 * q_sel]));
        if ((lane & 1) == 0)
            *reinterpret_cast<ull*>(&szr[w][r_sel][2 * q_sel]) = Z;
        __syncwarp();

        // ---- residual update: halves split the r's, one dim t per lane ----
        #pragma unroll
        for (int rr = 0; rr < 2; rr++) {
            const int r = rbase + rr;
            ull d2 = pack2(gbb, 0.f);
            #pragma unroll
            for (int q = 0; q < 4; q++)
                d2 = fma2(lds64(&szr[w][r][2 * q]), gwr[q], d2);
            float lo, hi; unpack2(d2, lo, hi);
            sx[w + 8 * r][lt] += lo + hi;
        }
        __syncwarp();
    }
    __syncthreads();

    // ---- orbital projection + sum over electrons ----
    float v = 0.f;
    #pragma unroll
    for (int t = tid; t < 512; t += 256)
        v += sx[t >> 4][t & 15] * sorb[t & 15];
    v += __shfl_xor_sync(M, v, 16);
    v += __shfl_xor_sync(M, v, 8);
    v += __shfl_xor_sync(M, v, 4);
    v += __shfl_xor_sync(M, v, 2);
    v += __shfl_xor_sync(M, v, 1);
    if (lane == 0) spart[w] = v;
    __syncthreads();
    if (tid == 0) {
        float s2 = 0.f;
        #pragma unroll
        for (int q = 0; q < 8; q++) s2 += spart[q];
        out[b] = s2;
    }
}

extern "C" void kernel_launch(void* const* d_in, const int* in_sizes, int n_in,
                              void* d_out, int out_size)
{
    const float* dn   = (const float*)d_in[0];
    const float* de   = (const float*)d_in[1];
    const float* Xe   = (const float*)d_in[2];
    const float* Yn   = (const float*)d_in[3];
    const float* hsw  = (const float*)d_in[8];
    const float* hsb  = (const float*)d_in[9];
    const float* haw  = (const float*)d_in[10];
    const float* hab  = (const float*)d_in[11];
    const float* gw   = (const float*)d_in[12];
    const float* gb   = (const float*)d_in[13];
    const float* orb  = (const float*)d_in[14];
    float* out = (float*)d_out;

    // 1) transform pair-MLP weights on device, 2) copy into constant bank (DtoD)
    prep_kernel<<<1, 128>>>((const float*)d_in[4], (const float*)d_in[5],
                            (const float*)d_in[6], (const float*)d_in[7]);
    void* scratch = nullptr;
    cudaGetSymbolAddress(&scratch, d_wscratch);
    const float* sc = (const float*)scratch;
    cudaMemcpyToSymbolAsync(cW1p, sc,       48 * sizeof(float), 0, cudaMemcpyDeviceToDevice, 0);
    cudaMemcpyToSymbolAsync(cB1p, sc + 48,  12 * sizeof(float), 0, cudaMemcpyDeviceToDevice, 0);
    cudaMemcpyToSymbolAsync(cW2p, sc + 60,  96 * sizeof(float), 0, cudaMemcpyDeviceToDevice, 0);
    cudaMemcpyToSymbolAsync(cB2p, sc + 156, 16 * sizeof(float), 0, cudaMemcpyDeviceToDevice, 0);

    const int B = in_sizes[0] / (32 * 8 * 4);   // dists_nuc: (B,32,8,4)

    dim3 blk(32, 8);
    omni_kernel<<<B, blk>>>(dn, de, Xe, Yn,
                            hsw, hsb, haw, hab, gw, gb, orb, out);
}

// round 7
// speedup vs baseline: 4.8979x; 1.1110x over previous
#include <cuda_runtime.h>

#define LN2  0.69314718055994531f
#define L2E  1.4426950408889634f
typedef unsigned long long ull;

// Transformed warp-uniform weights, single constant struct (one DtoD copy):
//   W1p/B1p pre-scaled by log2(e); W2p pre-scaled by ln2; B2p absorbs -ln2*colsum(W2)
struct CP {
    ull W1p[2][12];   // floats   0..47   [n][d*3 + upair]
    ull B1p[2][3];    // floats  48..59
    ull W2p[2][24];   // floats  60..155  [n][u*4 + kpair]
    ull B2p[2][4];    // floats 156..171
};
__constant__ CP cp;

__device__ float d_wscratch[172];

__global__ void prep_kernel(const float* __restrict__ w1, const float* __restrict__ wb1,
                            const float* __restrict__ w2, const float* __restrict__ wb2)
{
    const int t = threadIdx.x;
    if (t < 48) d_wscratch[t]      = w1[t]  * L2E;
    if (t < 12) d_wscratch[48 + t] = wb1[t] * L2E;
    if (t < 96) d_wscratch[60 + t] = w2[t]  * LN2;
    if (t < 16) {
        const int n = t >> 3, k = t & 7;
        float s = 0.f;
        #pragma unroll
        for (int u = 0; u < 6; u++) s += w2[n * 48 + u * 8 + k];
        d_wscratch[156 + t] = wb2[t] - LN2 * s;
    }
}

__device__ __forceinline__ ull fma2(ull a, ull b, ull c) {
    ull d; asm("fma.rn.f32x2 %0,%1,%2,%3;" : "=l"(d) : "l"(a), "l"(b), "l"(c)); return d;
}
__device__ __forceinline__ ull mul2(ull a, ull b) {
    ull d; asm("mul.rn.f32x2 %0,%1,%2;" : "=l"(d) : "l"(a), "l"(b)); return d;
}
__device__ __forceinline__ ull add2(ull a, ull b) {
    ull d; asm("add.rn.f32x2 %0,%1,%2;" : "=l"(d) : "l"(a), "l"(b)); return d;
}
__device__ __forceinline__ ull pack2(float lo, float hi) {
    ull d; asm("mov.b64 %0,{%1,%2};" : "=l"(d) : "f"(lo), "f"(hi)); return d;
}
__device__ __forceinline__ void unpack2(ull v, float& lo, float& hi) {
    asm("mov.b64 {%0,%1},%2;" : "=f"(lo), "=f"(hi) : "l"(v));
}
__device__ __forceinline__ ull lds64(const float* p) {
    return *reinterpret_cast<const ull*>(p);
}
// log2(1 + 2^t): EX2 -> FADD -> LG2
__device__ __forceinline__ float lg1p2(float t) {
    float e, r;
    asm("ex2.approx.f32 %0, %1;" : "=f"(e) : "f"(t));
    asm("lg2.approx.f32 %0, %1;" : "=f"(r) : "f"(1.0f + e));
    return r;
}

// pair MLP 4->6(lg-SSP)->8 for one (i,j), times spin coef, times self-mask
__device__ __forceinline__ void pair_mlp(int n, const float4& e, const ull* coefr,
                                         bool selfj, ull* A)
{
    const ull e0 = pack2(e.x, e.x), e1 = pack2(e.y, e.y),
              e2 = pack2(e.z, e.z), e3 = pack2(e.w, e.w);
    const float mkf = selfj ? 0.f : 1.f;
    const ull m2 = pack2(mkf, mkf);
    float a[6];
    #pragma unroll
    for (int p = 0; p < 3; p++) {
        ull v2 = cp.B1p[n][p];
        v2 = fma2(e0, cp.W1p[n][p],     v2);
        v2 = fma2(e1, cp.W1p[n][3 + p], v2);
        v2 = fma2(e2, cp.W1p[n][6 + p], v2);
        v2 = fma2(e3, cp.W1p[n][9 + p], v2);
        float lo, hi; unpack2(v2, lo, hi);
        a[2 * p] = lg1p2(lo); a[2 * p + 1] = lg1p2(hi);
    }
    #pragma unroll
    for (int q = 0; q < 4; q++) A[q] = cp.B2p[n][q];
    #pragma unroll
    for (int u = 0; u < 6; u++) {
        const ull ad = pack2(a[u], a[u]);
        #pragma unroll
        for (int q = 0; q < 4; q++) A[q] = fma2(ad, cp.W2p[n][u * 4 + q], A[q]);
    }
    #pragma unroll
    for (int q = 0; q < 4; q++) A[q] = mul2(mul2(A[q], coefr[q]), m2);
}

__global__ __launch_bounds__(256, 3)
void omni_kernel(const float* __restrict__ dn, const float* __restrict__ de,
                 const float* __restrict__ Xe, const float* __restrict__ Yn,
                 const float* __restrict__ hsw, const float* __restrict__ hsb,
                 const float* __restrict__ haw, const float* __restrict__ hab,
                 const float* __restrict__ gw, const float* __restrict__ gb,
                 const float* __restrict__ orb, float* __restrict__ out)
{
    const int b    = blockIdx.x;
    const int lane = threadIdx.x;        // partner electron j
    const int w    = threadIdx.y;        // warp w owns i = w + 8r, r=0..3
    const int tid  = (w << 5) | lane;
    const unsigned M = 0xffffffffu;

    __shared__ float shwT[2][2][8][18];  // [n][s][k][d] pairs (72B stride)
    __shared__ float shb[2][2][8];
    __shared__ float sgwT[2][16][10];    // [n][t][k] pairs (40B stride)
    __shared__ float sgb[2][16];
    __shared__ float sY[64];             // [m*8+k]
    __shared__ float sorb[16];
    __shared__ float sx[32][16];         // embeddings
    __shared__ float sc2[2][2][32][10];  // [n][spin][j][k] pairs
    __shared__ float sznuc[2][32][8];
    __shared__ float szr[8][4][8];       // per-warp z buffer [w][r][k]
    __shared__ float spart[8];

    // ---- stage lane-indexed weights ----
    #pragma unroll
    for (int t = tid; t < 512; t += 256) {
        const int n = t >> 8, r0 = t & 255, s = r0 >> 7, r2 = r0 & 127, k = r2 >> 4, d = r2 & 15;
        shwT[n][s][k][d] = (s ? haw : hsw)[n * 128 + d * 8 + k];
    }
    {
        const int n = tid >> 7, r0 = tid & 127, t = r0 >> 3, k = r0 & 7;
        sgwT[n][t][k] = gw[n * 128 + k * 16 + t];
    }
    if (tid < 16) { const int n = tid >> 3, k = tid & 7; shb[n][0][k] = hsb[tid]; shb[n][1][k] = hab[tid]; }
    if (tid < 32) ((float*)sgb)[tid] = gb[tid];
    if (tid < 64) sY[tid]   = Yn[tid];
    if (tid < 16) sorb[tid] = orb[tid];
    #pragma unroll
    for (int t = tid; t < 512; t += 256) sx[t >> 4][t & 15] = Xe[t & 15];

    // pair distance features for 4 i's
    float4 ee[4];
    #pragma unroll
    for (int r = 0; r < 4; r++)
        ee[r] = *reinterpret_cast<const float4*>(
            &de[(((size_t)b * 32 + (w + 8 * r)) * 32 + lane) << 2]);
    __syncthreads();

    // ---- nuclear messages: en loaded once for both interactions ----
    {
        const int ii = tid >> 3, m = tid & 7;
        const float4 en = *reinterpret_cast<const float4*>(
            &dn[(((size_t)b * 32 + ii) * 8 + m) << 2]);
        const ull e0 = pack2(en.x, en.x), e1 = pack2(en.y, en.y),
                  e2 = pack2(en.z, en.z), e3 = pack2(en.w, en.w);
        ull sy[4];
        #pragma unroll
        for (int q = 0; q < 4; q++) sy[q] = lds64(&sY[m * 8 + 2 * q]);
        const bool h4 = (m & 4), h2 = (m & 2);
        const int qc = (m >> 1) & 3;
        #pragma unroll
        for (int n = 0; n < 2; n++) {
            float a[6];
            #pragma unroll
            for (int p = 0; p < 3; p++) {
                ull v2 = cp.B1p[n][p];
                v2 = fma2(e0, cp.W1p[n][p],     v2);
                v2 = fma2(e1, cp.W1p[n][3 + p], v2);
                v2 = fma2(e2, cp.W1p[n][6 + p], v2);
                v2 = fma2(e3, cp.W1p[n][9 + p], v2);
                float lo, hi; unpack2(v2, lo, hi);
                a[2 * p] = lg1p2(lo); a[2 * p + 1] = lg1p2(hi);
            }
            ull A[4];
            #pragma unroll
            for (int q = 0; q < 4; q++) A[q] = cp.B2p[n][q];
            #pragma unroll
            for (int u = 0; u < 6; u++) {
                const ull ad = pack2(a[u], a[u]);
                #pragma unroll
                for (int q = 0; q < 4; q++) A[q] = fma2(ad, cp.W2p[n][u * 4 + q], A[q]);
            }
            #pragma unroll
            for (int q = 0; q < 4; q++) A[q] = mul2(A[q], sy[q]);
            ull s;
            #pragma unroll
            for (int q = 0; q < 2; q++) {
                s = __shfl_xor_sync(M, h4 ? A[q] : A[q + 2], 4);
                A[q] = add2(h4 ? A[q + 2] : A[q], s);
            }
            s = __shfl_xor_sync(M, h2 ? A[0] : A[1], 2);
            A[0] = add2(h2 ? A[1] : A[0], s);
            A[0] = add2(A[0], __shfl_xor_sync(M, A[0], 1));
            if ((m & 1) == 0)
                *reinterpret_cast<ull*>(&sznuc[n][ii][2 * qc]) = A[0];
        }
    }
    __syncthreads();

    const int  sH    = (lane >> 3) & 1;
    const int  kH    = lane & 7;
    const int  rbase = (lane >> 4) << 1;
    const int  lt    = lane & 15;
    const bool b4 = (lane & 16), b3 = (lane & 8), b2 = (lane & 4), b1 = (lane & 2);
    const int  r_sel = ((lane >> 3) & 2) | ((lane >> 3) & 1);   // 2*b4 + b3
    const int  q_sel = (lane >> 1) & 3;                         // 2*b2 + b1

    #pragma unroll
    for (int n = 0; n < 2; n++) {
        // ---- h features (all 32 lanes busy) ----
        {
            ull wh[8];
            #pragma unroll
            for (int d2 = 0; d2 < 8; d2++) wh[d2] = lds64(&shwT[n][sH][kH][2 * d2]);
            const float bb = shb[n][sH][kH];
            #pragma unroll
            for (int rr = 0; rr < 2; rr++) {
                const int r = rbase + rr;
                const int i = w + 8 * r;
                ull acc = pack2(bb, 0.f);
                #pragma unroll
                for (int d2 = 0; d2 < 8; d2++)
                    acc = fma2(lds64(&sx[i][2 * d2]), wh[d2], acc);
                float lo, hi; unpack2(acc, lo, hi);
                sc2[n][sH ^ (r >> 1)][i][kH] = lo + hi;
            }
        }
        __syncthreads();

        // coef rows depend only on spin group
        ull coef[2][4];
        #pragma unroll
        for (int gg = 0; gg < 2; gg++)
            #pragma unroll
            for (int q = 0; q < 4; q++) coef[gg][q] = lds64(&sc2[n][gg][lane][2 * q]);

        // ---- combined fold: 16 values (4r x 4q) over 5 rounds ----
        ull F0[4], F1[4], Z;
        {   // stage 1: r=0 and r=2, fold over xor16 (keeps r = 2*b4)
            ull A0[4], A2[4];
            pair_mlp(n, ee[0], coef[0], lane == w,      A0);
            pair_mlp(n, ee[2], coef[1], lane == w + 16, A2);
            #pragma unroll
            for (int q = 0; q < 4; q++) {
                const ull s = __shfl_xor_sync(M, b4 ? A0[q] : A2[q], 16);
                F0[q] = add2(b4 ? A2[q] : A0[q], s);
            }
        }
        {   // stage 2: r=1 and r=3 (keeps r = 2*b4 + 1)
            ull A1[4], A3[4];
            pair_mlp(n, ee[1], coef[0], lane == w + 8,  A1);
            pair_mlp(n, ee[3], coef[1], lane == w + 24, A3);
            #pragma unroll
            for (int q = 0; q < 4; q++) {
                const ull s = __shfl_xor_sync(M, b4 ? A1[q] : A3[q], 16);
                F1[q] = add2(b4 ? A3[q] : A1[q], s);
            }
        }
        // round 2 (xor8): r-bit0 = b3
        #pragma unroll
        for (int q = 0; q < 4; q++) {
            const ull s = __shfl_xor_sync(M, b3 ? F0[q] : F1[q], 8);
            F0[q] = add2(b3 ? F1[q] : F0[q], s);
        }
        // round 3 (xor4): q-bit1 = b2
        {
            ull s = __shfl_xor_sync(M, b2 ? F0[0] : F0[2], 4);
            F0[0] = add2(b2 ? F0[2] : F0[0], s);
            s = __shfl_xor_sync(M, b2 ? F0[1] : F0[3], 4);
            F0[1] = add2(b2 ? F0[3] : F0[1], s);
        }
        // round 4 (xor2): q-bit0 = b1 ; round 5 (xor1): butterfly
        {
            ull s = __shfl_xor_sync(M, b1 ? F0[0] : F0[1], 2);
            Z = add2(b1 ? F0[1] : F0[0], s);
            Z = add2(Z, __shfl_xor_sync(M, Z, 1));
        }
        // add nuclear message, publish z(r_sel, q_sel) to per-warp buffer
        Z = add2(Z, lds64(&sznuc[n][w + 8 * r_sel][2 * q_sel]));
        if ((lane & 1) == 0)
            *reinterpret_cast<ull*>(&szr[w][r_sel][2 * q_sel]) = Z;
        __syncwarp();

        // ---- residual update (g weights loaded late: short live range) ----
        {
            ull gwr[4];
            #pragma unroll
            for (int q = 0; q < 4; q++) gwr[q] = lds64(&sgwT[n][lt][2 * q]);
            const float gbb = sgb[n][lt];
            #pragma unroll
            for (int rr = 0; rr < 2; rr++) {
                const int r = rbase + rr;
                ull d2 = pack2(gbb, 0.f);
                #pragma unroll
                for (int q = 0; q < 4; q++)
                    d2 = fma2(lds64(&szr[w][r][2 * q]), gwr[q], d2);
                float lo, hi; unpack2(d2, lo, hi);
                sx[w + 8 * r][lt] += lo + hi;
            }
        }
        __syncwarp();
    }
    __syncthreads();

    // ---- orbital projection + sum over electrons ----
    float v = 0.f;
    #pragma unroll
    for (int t = tid; t < 512; t += 256)
        v += sx[t >> 4][t & 15] * sorb[t & 15];
    v += __shfl_xor_sync(M, v, 16);
    v += __shfl_xor_sync(M, v, 8);
    v += __shfl_xor_sync(M, v, 4);
    v += __shfl_xor_sync(M, v, 2);
    v += __shfl_xor_sync(M, v, 1);
    if (lane == 0) spart[w] = v;
    __syncthreads();
    if (tid == 0) {
        float s2 = 0.f;
        #pragma unroll
        for (int q = 0; q < 8; q++) s2 += spart[q];
        out[b] = s2;
    }
}

extern "C" void kernel_launch(void* const* d_in, const int* in_sizes, int n_in,
                              void* d_out, int out_size)
{
    const float* dn   = (const float*)d_in[0];
    const float* de   = (const float*)d_in[1];
    const float* Xe   = (const float*)d_in[2];
    const float* Yn   = (const float*)d_in[3];
    const float* hsw  = (const float*)d_in[8];
    const float* hsb  = (const float*)d_in[9];
    const float* haw  = (const float*)d_in[10];
    const float* hab  = (const float*)d_in[11];
    const float* gw   = (const float*)d_in[12];
    const float* gb   = (const float*)d_in[13];
    const float* orb  = (const float*)d_in[14];
    float* out = (float*)d_out;

    // transform pair-MLP weights on device, then ONE DtoD copy into the constant struct
    prep_kernel<<<1, 128>>>((const float*)d_in[4], (const float*)d_in[5],
                            (const float*)d_in[6], (const float*)d_in[7]);
    void* scratch = nullptr;
    cudaGetSymbolAddress(&scratch, d_wscratch);
    cudaMemcpyToSymbolAsync(cp, scratch, 172 * sizeof(float), 0, cudaMemcpyDeviceToDevice, 0);

    const int B = in_sizes[0] / (32 * 8 * 4);   // dists_nuc: (B,32,8,4)

    dim3 blk(32, 8);
    omni_kernel<<<B, blk>>>(dn, de, Xe, Yn,
                            hsw, hsb, haw, hab, gw, gb, orb, out);
}

// round 10
// speedup vs baseline: 5.2322x; 1.0683x over previous
#include <cuda_runtime.h>

#define LN2  0.69314718055994531f
#define L2E  1.4426950408889634f
typedef unsigned long long ull;

// Transformed warp-uniform weights, single constant struct (one DtoD copy):
//   W1p/B1p pre-scaled by log2(e); W2p pre-scaled by ln2; B2p absorbs -ln2*colsum(W2)
struct CP {
    ull W1p[2][12];   // [n][d*3 + upair]
    ull B1p[2][3];
    ull W2p[2][24];   // [n][u*4 + kpair]
    ull B2p[2][4];
};
__constant__ CP cp;

__device__ float d_wscratch[172];

__global__ void prep_kernel(const float* __restrict__ w1, const float* __restrict__ wb1,
                            const float* __restrict__ w2, const float* __restrict__ wb2)
{
    const int t = threadIdx.x;
    if (t < 48) d_wscratch[t]      = w1[t]  * L2E;
    if (t < 12) d_wscratch[48 + t] = wb1[t] * L2E;
    if (t < 96) d_wscratch[60 + t] = w2[t]  * LN2;
    if (t < 16) {
        const int n = t >> 3, k = t & 7;
        float s = 0.f;
        #pragma unroll
        for (int u = 0; u < 6; u++) s += w2[n * 48 + u * 8 + k];
        d_wscratch[156 + t] = wb2[t] - LN2 * s;
    }
}

__device__ __forceinline__ ull fma2(ull a, ull b, ull c) {
    ull d; asm("fma.rn.f32x2 %0,%1,%2,%3;" : "=l"(d) : "l"(a), "l"(b), "l"(c)); return d;
}
__device__ __forceinline__ ull mul2(ull a, ull b) {
    ull d; asm("mul.rn.f32x2 %0,%1,%2;" : "=l"(d) : "l"(a), "l"(b)); return d;
}
__device__ __forceinline__ ull add2(ull a, ull b) {
    ull d; asm("add.rn.f32x2 %0,%1,%2;" : "=l"(d) : "l"(a), "l"(b)); return d;
}
__device__ __forceinline__ ull pack2(float lo, float hi) {
    ull d; asm("mov.b64 %0,{%1,%2};" : "=l"(d) : "f"(lo), "f"(hi)); return d;
}
__device__ __forceinline__ void unpack2(ull v, float& lo, float& hi) {
    asm("mov.b64 {%0,%1},%2;" : "=f"(lo), "=f"(hi) : "l"(v));
}
__device__ __forceinline__ ull lds64(const float* p) {
    return *reinterpret_cast<const ull*>(p);
}
// log2(1 + 2^t): EX2 -> FADD -> LG2
__device__ __forceinline__ float lg1p2(float t) {
    float e, r;
    asm("ex2.approx.f32 %0, %1;" : "=f"(e) : "f"(t));
    asm("lg2.approx.f32 %0, %1;" : "=f"(r) : "f"(1.0f + e));
    return r;
}

// pair MLP 4->6(lg-SSP)->8, times spin coef (smem ptr), times self-mask
__device__ __forceinline__ void pair_mlp(int n, const float4& e, const float* coefp,
                                         bool selfj, ull* A)
{
    const ull e0 = pack2(e.x, e.x), e1 = pack2(e.y, e.y),
              e2 = pack2(e.z, e.z), e3 = pack2(e.w, e.w);
    const float mkf = selfj ? 0.f : 1.f;
    const ull m2 = pack2(mkf, mkf);
    float a[6];
    #pragma unroll
    for (int p = 0; p < 3; p++) {
        ull v2 = cp.B1p[n][p];
        v2 = fma2(e0, cp.W1p[n][p],     v2);
        v2 = fma2(e1, cp.W1p[n][3 + p], v2);
        v2 = fma2(e2, cp.W1p[n][6 + p], v2);
        v2 = fma2(e3, cp.W1p[n][9 + p], v2);
        float lo, hi; unpack2(v2, lo, hi);
        a[2 * p] = lg1p2(lo); a[2 * p + 1] = lg1p2(hi);
    }
    #pragma unroll
    for (int q = 0; q < 4; q++) A[q] = cp.B2p[n][q];
    #pragma unroll
    for (int u = 0; u < 6; u++) {
        const ull ad = pack2(a[u], a[u]);
        #pragma unroll
        for (int q = 0; q < 4; q++) A[q] = fma2(ad, cp.W2p[n][u * 4 + q], A[q]);
    }
    #pragma unroll
    for (int q = 0; q < 4; q++) A[q] = mul2(mul2(A[q], lds64(coefp + 2 * q)), m2);
}

__global__ __launch_bounds__(256, 3)
void omni_kernel(const float* __restrict__ dn, const float* __restrict__ de,
                 const float* __restrict__ Xe, const float* __restrict__ Yn,
                 const float* __restrict__ hsw, const float* __restrict__ hsb,
                 const float* __restrict__ haw, const float* __restrict__ hab,
                 const float* __restrict__ gw, const float* __restrict__ gb,
                 const float* __restrict__ orb, float* __restrict__ out)
{
    const int b    = blockIdx.x;
    const int lane = threadIdx.x;        // partner electron j
    const int w    = threadIdx.y;        // warp w owns i = w + 8r, r=0..3
    const int tid  = (w << 5) | lane;
    const unsigned M = 0xffffffffu;

    __shared__ float shwT[2][2][8][18];  // [n][s][k][d] pairs (72B stride)
    __shared__ float shb[2][2][8];
    __shared__ float sgwT[2][16][10];    // [n][t][k] pairs (40B stride)
    __shared__ float sgb[2][16];
    __shared__ float sY[64];             // [m*8+k]
    __shared__ float sorb[16];
    __shared__ float sx[32][16];         // embeddings
    __shared__ float sc2[2][2][32][10];  // [n][spin][j][k] pairs
    __shared__ float sznuc[2][32][8];
    __shared__ float szr[8][4][8];       // per-warp z buffer [w][r][k]
    __shared__ float spart[8];

    // ---- stage lane-indexed weights ----
    #pragma unroll
    for (int t = tid; t < 512; t += 256) {
        const int n = t >> 8, r0 = t & 255, s = r0 >> 7, r2 = r0 & 127, k = r2 >> 4, d = r2 & 15;
        shwT[n][s][k][d] = (s ? haw : hsw)[n * 128 + d * 8 + k];
    }
    {
        const int n = tid >> 7, r0 = tid & 127, t = r0 >> 3, k = r0 & 7;
        sgwT[n][t][k] = gw[n * 128 + k * 16 + t];
    }
    if (tid < 16) { const int n = tid >> 3, k = tid & 7; shb[n][0][k] = hsb[tid]; shb[n][1][k] = hab[tid]; }
    if (tid < 32) ((float*)sgb)[tid] = gb[tid];
    if (tid < 64) sY[tid]   = Yn[tid];
    if (tid < 16) sorb[tid] = orb[tid];
    #pragma unroll
    for (int t = tid; t < 512; t += 256) sx[t >> 4][t & 15] = Xe[t & 15];

    // lane-permuted r assignment: slot order (KA, SA, KB, SB) = r_sel ^ {0,2,1,3}
    const int r_sel = (lane >> 3) & 3;
    const int rKA = r_sel, rSA = r_sel ^ 2, rKB = r_sel ^ 1, rSB = r_sel ^ 3;
    const int b4f = (lane >> 4) & 1;
    const bool b2 = (lane & 4), b1 = (lane & 2);
    const int q_sel = (lane >> 1) & 3;

    // pair distance features, loaded in permuted r-order (kept for both interactions)
    float4 eKA, eSA, eKB, eSB;
    {
        const size_t base = ((size_t)b * 32) * 32 + lane;
        eKA = *reinterpret_cast<const float4*>(&de[(base + 32 * (w + 8 * rKA)) << 2]);
        eSA = *reinterpret_cast<const float4*>(&de[(base + 32 * (w + 8 * rSA)) << 2]);
        eKB = *reinterpret_cast<const float4*>(&de[(base + 32 * (w + 8 * rKB)) << 2]);
        eSB = *reinterpret_cast<const float4*>(&de[(base + 32 * (w + 8 * rSB)) << 2]);
    }
    __syncthreads();

    // ---- nuclear messages: en loaded once for both interactions ----
    {
        const int ii = tid >> 3, m = tid & 7;
        const float4 en = *reinterpret_cast<const float4*>(
            &dn[(((size_t)b * 32 + ii) * 8 + m) << 2]);
        const ull e0 = pack2(en.x, en.x), e1 = pack2(en.y, en.y),
                  e2 = pack2(en.z, en.z), e3 = pack2(en.w, en.w);
        ull sy[4];
        #pragma unroll
        for (int q = 0; q < 4; q++) sy[q] = lds64(&sY[m * 8 + 2 * q]);
        const bool h4 = (m & 4), h2 = (m & 2);
        const int qc = (m >> 1) & 3;
        #pragma unroll
        for (int n = 0; n < 2; n++) {
            float a[6];
            #pragma unroll
            for (int p = 0; p < 3; p++) {
                ull v2 = cp.B1p[n][p];
                v2 = fma2(e0, cp.W1p[n][p],     v2);
                v2 = fma2(e1, cp.W1p[n][3 + p], v2);
                v2 = fma2(e2, cp.W1p[n][6 + p], v2);
                v2 = fma2(e3, cp.W1p[n][9 + p], v2);
                float lo, hi; unpack2(v2, lo, hi);
                a[2 * p] = lg1p2(lo); a[2 * p + 1] = lg1p2(hi);
            }
            ull A[4];
            #pragma unroll
            for (int q = 0; q < 4; q++) A[q] = cp.B2p[n][q];
            #pragma unroll
            for (int u = 0; u < 6; u++) {
                const ull ad = pack2(a[u], a[u]);
                #pragma unroll
                for (int q = 0; q < 4; q++) A[q] = fma2(ad, cp.W2p[n][u * 4 + q], A[q]);
            }
            #pragma unroll
            for (int q = 0; q < 4; q++) A[q] = mul2(A[q], sy[q]);
            ull s;
            #pragma unroll
            for (int q = 0; q < 2; q++) {
                s = __shfl_xor_sync(M, h4 ? A[q] : A[q + 2], 4);
                A[q] = add2(h4 ? A[q + 2] : A[q], s);
            }
            s = __shfl_xor_sync(M, h2 ? A[0] : A[1], 2);
            A[0] = add2(h2 ? A[1] : A[0], s);
            A[0] = add2(A[0], __shfl_xor_sync(M, A[0], 1));
            if ((m & 1) == 0)
                *reinterpret_cast<ull*>(&sznuc[n][ii][2 * qc]) = A[0];
        }
    }
    __syncthreads();

    const int sH    = (lane >> 3) & 1;
    const int kH    = lane & 7;
    const int rbase = (lane >> 4) << 1;
    const int lt    = lane & 15;

    #pragma unroll
    for (int n = 0; n < 2; n++) {
        // ---- h features (all 32 lanes busy) ----
        {
            ull wh[8];
            #pragma unroll
            for (int d2 = 0; d2 < 8; d2++) wh[d2] = lds64(&shwT[n][sH][kH][2 * d2]);
            const float bb = shb[n][sH][kH];
            #pragma unroll
            for (int rr = 0; rr < 2; rr++) {
                const int r = rbase + rr;
                const int i = w + 8 * r;
                ull acc = pack2(bb, 0.f);
                #pragma unroll
                for (int d2 = 0; d2 < 8; d2++)
                    acc = fma2(lds64(&sx[i][2 * d2]), wh[d2], acc);
                float lo, hi; unpack2(acc, lo, hi);
                sc2[n][sH ^ (r >> 1)][i][kH] = lo + hi;
            }
        }
        __syncthreads();

        // coef base addresses (variable gg index, no selects)
        const float* coefK = &sc2[n][b4f][lane][0];       // gg = rK>>1 = b4
        const float* coefS = &sc2[n][1 - b4f][lane][0];   // gg = rS>>1 = 1-b4

        // ---- select-free fold rounds 1-2 via permuted slots ----
        ull E[4];
        {
            ull KA[4], SA[4], FA[4];
            pair_mlp(n, eKA, coefK, lane == w + 8 * rKA, KA);
            pair_mlp(n, eSA, coefS, lane == w + 8 * rSA, SA);
            #pragma unroll
            for (int q = 0; q < 4; q++)
                FA[q] = add2(KA[q], __shfl_xor_sync(M, SA[q], 16));
            ull KB[4], SB[4];
            pair_mlp(n, eKB, coefK, lane == w + 8 * rKB, KB);
            pair_mlp(n, eSB, coefS, lane == w + 8 * rSB, SB);
            #pragma unroll
            for (int q = 0; q < 4; q++) {
                const ull FB = add2(KB[q], __shfl_xor_sync(M, SB[q], 16));
                E[q] = add2(FA[q], __shfl_xor_sync(M, FB, 8));
            }
        }
        // round 3 (xor4): q-bit1 = b2
        ull G0, G1;
        {
            const ull K0 = b2 ? E[2] : E[0], S0 = b2 ? E[0] : E[2];
            const ull K1 = b2 ? E[3] : E[1], S1 = b2 ? E[1] : E[3];
            G0 = add2(K0, __shfl_xor_sync(M, S0, 4));
            G1 = add2(K1, __shfl_xor_sync(M, S1, 4));
        }
        // round 4 (xor2): q-bit0 = b1 ; round 5 (xor1): butterfly
        ull Z;
        {
            const ull K = b1 ? G1 : G0, S = b1 ? G0 : G1;
            Z = add2(K, __shfl_xor_sync(M, S, 2));
            Z = add2(Z, __shfl_xor_sync(M, Z, 1));
        }
        // add nuclear message, publish z(r_sel, q_sel) to per-warp buffer
        Z = add2(Z, lds64(&sznuc[n][w + 8 * r_sel][2 * q_sel]));
        if ((lane & 1) == 0)
            *reinterpret_cast<ull*>(&szr[w][r_sel][2 * q_sel]) = Z;
        __syncwarp();

        // ---- residual update (g weights loaded late: short live range) ----
        {
            ull gwr[4];
            #pragma unroll
            for (int q = 0; q < 4; q++) gwr[q] = lds64(&sgwT[n][lt][2 * q]);
            const float gbb = sgb[n][lt];
            #pragma unroll
            for (int rr = 0; rr < 2; rr++) {
                const int r = rbase + rr;
                ull d2 = pack2(gbb, 0.f);
                #pragma unroll
                for (int q = 0; q < 4; q++)
                    d2 = fma2(lds64(&szr[w][r][2 * q]), gwr[q], d2);
                float lo, hi; unpack2(d2, lo, hi);
                sx[w + 8 * r][lt] += lo + hi;
            }
        }
        __syncwarp();
    }
    __syncthreads();

    // ---- orbital projection + sum over electrons ----
    float v = 0.f;
    #pragma unroll
    for (int t = tid; t < 512; t += 256)
        v += sx[t >> 4][t & 15] * sorb[t & 15];
    v += __shfl_xor_sync(M, v, 16);
    v += __shfl_xor_sync(M, v, 8);
    v += __shfl_xor_sync(M, v, 4);
    v += __shfl_xor_sync(M, v, 2);
    v += __shfl_xor_sync(M, v, 1);
    if (lane == 0) spart[w] = v;
    __syncthreads();
    if (tid == 0) {
        float s2 = 0.f;
        #pragma unroll
        for (int q = 0; q < 8; q++) s2 += spart[q];
        out[b] = s2;
    }
}

extern "C" void kernel_launch(void* const* d_in, const int* in_sizes, int n_in,
                              void* d_out, int out_size)
{
    const float* dn   = (const float*)d_in[0];
    const float* de   = (const float*)d_in[1];
    const float* Xe   = (const float*)d_in[2];
    const float* Yn   = (const float*)d_in[3];
    const float* hsw  = (const float*)d_in[8];
    const float* hsb  = (const float*)d_in[9];
    const float* haw  = (const float*)d_in[10];
    const float* hab  = (const float*)d_in[11];
    const float* gw   = (const float*)d_in[12];
    const float* gb   = (const float*)d_in[13];
    const float* orb  = (const float*)d_in[14];
    float* out = (float*)d_out;

    // transform pair-MLP weights on device, then ONE DtoD copy into the constant struct
    prep_kernel<<<1, 128>>>((const float*)d_in[4], (const float*)d_in[5],
                            (const float*)d_in[6], (const float*)d_in[7]);
    void* scratch = nullptr;
    cudaGetSymbolAddress(&scratch, d_wscratch);
    cudaMemcpyToSymbolAsync(cp, scratch, 172 * sizeof(float), 0, cudaMemcpyDeviceToDevice, 0);

    const int B = in_sizes[0] / (32 * 8 * 4);   // dists_nuc: (B,32,8,4)

    dim3 blk(32, 8);
    omni_kernel<<<B, blk>>>(dn, de, Xe, Yn,
                            hsw, hsb, haw, hab, gw, gb, orb, out);
}